// round 1
// baseline (speedup 1.0000x reference)
#include <cuda_runtime.h>
#include <math.h>

// Problem dims
#define BD   8192
#define TT   8
#define EE   256
#define GG   1024          // 4*E
#define MM   20
#define ROWS (BD*MM)       // 163840
#define FSX  12
#define PRED_ELEMS (BD*MM*FSX*2)   // 3932160

// ---------------- scratch (static device globals; no allocation) -------------
__device__ float g_ys0[(size_t)TT*BD*EE];      // layer0 outputs, (t,b,e)
__device__ float g_xh1[(size_t)TT*BD*GG];      // precomputed x@w_ih1.T for layer1
__device__ float g_h0[BD*EE];
__device__ float g_c0[BD*EE];
__device__ float g_h1[BD*EE];                  // final value == emb
__device__ float g_c1[BD*EE];
__device__ float g_gates[(size_t)BD*GG];
__device__ float g_bufA[(size_t)ROWS*EE];      // v/ctx, ln1-out, mm_emb
__device__ float g_bufB[(size_t)ROWS*EE];      // attn_out, ffn2-out, sc hidden
__device__ float g_bufC[(size_t)ROWS*1024];    // ffn hidden / dec hidden

// ---------------- generic fp32 NT GEMM: C[r,n] = sum_k A[r,k]*W[n,k] --------
// ACT: 0=none 1=relu 2=elu
template<int BM,int BN,int BK,int TM,int TN,int ACT>
__global__ void __launch_bounds__((BM/TM)*(BN/TN))
gemm_nt(const float* __restrict__ A, long sA, int lda,
        const float* __restrict__ W, long sW,
        const float* __restrict__ bias, long sBias,
        float* __restrict__ C, long sC, int ldc,
        int Mrows, int N, int K)
{
    constexpr int NT = (BM/TM)*(BN/TN);
    __shared__ float As[BK][BM];
    __shared__ float Ws[BK][BN];

    const float* Ab = A + (long)blockIdx.z * sA;
    const float* Wb = W + (long)blockIdx.z * sW;
    float*       Cb = C + (long)blockIdx.z * sC;

    const int row0 = blockIdx.y * BM;
    const int n0   = blockIdx.x * BN;
    const int tid  = threadIdx.x;
    const int tx   = tid % (BN/TN);
    const int ty   = tid / (BN/TN);

    float acc[TM][TN];
#pragma unroll
    for (int i = 0; i < TM; i++)
#pragma unroll
        for (int j = 0; j < TN; j++) acc[i][j] = 0.f;

    for (int kt = 0; kt < K; kt += BK) {
        // load A tile (rows always in-bounds: Mrows % BM == 0 for all calls)
#pragma unroll
        for (int idx = tid; idx < BM*BK/4; idx += NT) {
            int r  = (idx*4) / BK;
            int kk = (idx*4) % BK;
            float4 v = *(const float4*)(Ab + (long)(row0 + r)*lda + kt + kk);
            As[kk+0][r] = v.x; As[kk+1][r] = v.y; As[kk+2][r] = v.z; As[kk+3][r] = v.w;
        }
        // load W tile (guard N)
#pragma unroll
        for (int idx = tid; idx < BN*BK/4; idx += NT) {
            int n  = (idx*4) / BK;
            int kk = (idx*4) % BK;
            float4 v = make_float4(0.f,0.f,0.f,0.f);
            if (n0 + n < N)
                v = *(const float4*)(Wb + (long)(n0 + n)*K + kt + kk);
            Ws[kk+0][n] = v.x; Ws[kk+1][n] = v.y; Ws[kk+2][n] = v.z; Ws[kk+3][n] = v.w;
        }
        __syncthreads();

#pragma unroll
        for (int k = 0; k < BK; k++) {
            float a[TM], b[TN];
#pragma unroll
            for (int i = 0; i < TM; i++) a[i] = As[k][ty*TM + i];
#pragma unroll
            for (int j = 0; j < TN; j++) b[j] = Ws[k][tx*TN + j];
#pragma unroll
            for (int i = 0; i < TM; i++)
#pragma unroll
                for (int j = 0; j < TN; j++)
                    acc[i][j] = fmaf(a[i], b[j], acc[i][j]);
        }
        __syncthreads();
    }

#pragma unroll
    for (int i = 0; i < TM; i++) {
        int r = row0 + ty*TM + i;
#pragma unroll
        for (int j = 0; j < TN; j++) {
            int n = n0 + tx*TN + j;
            if (n < N) {
                float v = acc[i][j];
                if (bias) v += bias[(long)blockIdx.z*sBias + n];
                if (ACT == 1) v = v > 0.f ? v : 0.f;
                if (ACT == 2) v = v > 0.f ? v : expm1f(v);
                Cb[(long)r*ldc + n] = v;
            }
        }
    }
}

// ---------------- pointwise / small kernels ---------------------------------
__device__ __forceinline__ float sigf(float x) { return 1.f / (1.f + expf(-x)); }

__global__ void zero_hc_kernel()
{
    int i = blockIdx.x*blockDim.x + threadIdx.x;
    if (i < BD*EE) { g_h0[i]=0.f; g_c0[i]=0.f; g_h1[i]=0.f; g_c1[i]=0.f; }
}

// layer-0 LSTM cell: x is (b, t, 2); x-projection (K=2) fused here.
__global__ void lstm_cell0(const float* __restrict__ obs, const float* __restrict__ w_ih,
                           const float* __restrict__ b_ih, const float* __restrict__ b_hh, int t)
{
    int idx = blockIdx.x*blockDim.x + threadIdx.x;
    if (idx >= BD*EE) return;
    int b = idx >> 8, e = idx & 255;
    float x0 = obs[((long)b*TT + t)*2 + 0];
    float x1 = obs[((long)b*TT + t)*2 + 1];
    float gv[4];
#pragma unroll
    for (int q = 0; q < 4; q++) {
        int j = q*EE + e;
        gv[q] = g_gates[(long)b*GG + j] + x0*w_ih[2*j] + x1*w_ih[2*j+1] + b_ih[j] + b_hh[j];
    }
    float ig = sigf(gv[0]), fg = sigf(gv[1]), gg = tanhf(gv[2]), og = sigf(gv[3]);
    float cn = fg * g_c0[idx] + ig * gg;
    float hn = og * tanhf(cn);
    g_c0[idx] = cn; g_h0[idx] = hn;
    g_ys0[(size_t)t*BD*EE + idx] = hn;
}

// layer-1 LSTM cell: input projection precomputed in g_xh1.
__global__ void lstm_cell1(const float* __restrict__ b_ih, const float* __restrict__ b_hh, int t)
{
    int idx = blockIdx.x*blockDim.x + threadIdx.x;
    if (idx >= BD*EE) return;
    int b = idx >> 8, e = idx & 255;
    const size_t xbase = ((size_t)t*BD + b)*GG;
    float gv[4];
#pragma unroll
    for (int q = 0; q < 4; q++) {
        int j = q*EE + e;
        gv[q] = g_gates[(long)b*GG + j] + g_xh1[xbase + j] + b_ih[j] + b_hh[j];
    }
    float ig = sigf(gv[0]), fg = sigf(gv[1]), gg = tanhf(gv[2]), og = sigf(gv[3]);
    float cn = fg * g_c1[idx] + ig * gg;
    float hn = og * tanhf(cn);
    g_c1[idx] = cn; g_h1[idx] = hn;
}

// LayerNorm over E=256, one warp per row.
__global__ void ln_kernel(const float* __restrict__ x, const float* __restrict__ gam,
                          const float* __restrict__ bet, float* __restrict__ y)
{
    size_t warp = ((size_t)blockIdx.x*blockDim.x + threadIdx.x) >> 5;
    int lane = threadIdx.x & 31;
    if (warp >= (size_t)ROWS) return;
    const float* xr = x + warp*EE;
    float4 p0 = *(const float4*)(xr + lane*8);
    float4 p1 = *(const float4*)(xr + lane*8 + 4);
    float v[8] = {p0.x,p0.y,p0.z,p0.w,p1.x,p1.y,p1.z,p1.w};
    float s = 0.f, sq = 0.f;
#pragma unroll
    for (int i = 0; i < 8; i++) { s += v[i]; sq += v[i]*v[i]; }
#pragma unroll
    for (int o = 16; o; o >>= 1) {
        s  += __shfl_xor_sync(0xffffffffu, s,  o);
        sq += __shfl_xor_sync(0xffffffffu, sq, o);
    }
    float m   = s * (1.f/EE);
    float var = sq * (1.f/EE) - m*m;
    float inv = rsqrtf(var + 1e-5f);
    float* yr = y + warp*EE;
#pragma unroll
    for (int i = 0; i < 8; i++) {
        int e = lane*8 + i;
        yr[e] = (v[i] - m) * inv * gam[e] + bet[e];
    }
}

// predictions += last observed position (broadcast over M, FS)
__global__ void add_lastpos(float* __restrict__ pred, const float* __restrict__ obs)
{
    size_t idx = (size_t)blockIdx.x*blockDim.x + threadIdx.x;
    if (idx >= (size_t)PRED_ELEMS) return;
    size_t b = idx / (MM*FSX*2);
    int c = (int)(idx & 1);
    pred[idx] += obs[(b*TT + (TT-1))*2 + c];
}

// score head final dot: out[r] = dot(s[r,0:128], w) + b
__global__ void sc2_kernel(const float* __restrict__ s, const float* __restrict__ w,
                           const float* __restrict__ b2, float* __restrict__ outp)
{
    size_t gwarp = ((size_t)blockIdx.x*blockDim.x + threadIdx.x) >> 5;
    int lane = threadIdx.x & 31;
    if (gwarp >= (size_t)ROWS) return;
    const float* row = s + gwarp*128;
    float4 a  = *(const float4*)(row + lane*4);
    float4 ww = *(const float4*)(w   + lane*4);
    float acc = a.x*ww.x + a.y*ww.y + a.z*ww.z + a.w*ww.w;
#pragma unroll
    for (int o = 16; o; o >>= 1) acc += __shfl_xor_sync(0xffffffffu, acc, o);
    if (lane == 0) outp[gwarp] = acc + b2[0];
}

// ---------------- host-side helpers -----------------------------------------
static void gemm_big(int act,
                     const float* A, long sA, int lda,
                     const float* W, long sW,
                     const float* bias, long sBias,
                     float* C, long sC, int ldc,
                     int Mrows, int N, int K, int nb)
{
    dim3 g((N + 127)/128, Mrows/128, nb);
    dim3 b(256);
    switch (act) {
    case 0: gemm_nt<128,128,8,8,8,0><<<g,b>>>(A,sA,lda,W,sW,bias,sBias,C,sC,ldc,Mrows,N,K); break;
    case 1: gemm_nt<128,128,8,8,8,1><<<g,b>>>(A,sA,lda,W,sW,bias,sBias,C,sC,ldc,Mrows,N,K); break;
    case 2: gemm_nt<128,128,8,8,8,2><<<g,b>>>(A,sA,lda,W,sW,bias,sBias,C,sC,ldc,Mrows,N,K); break;
    }
}

extern "C" void kernel_launch(void* const* d_in, const int* in_sizes, int n_in,
                              void* d_out, int out_size)
{
    (void)in_sizes; (void)n_in; (void)out_size;
    const float* obs       = (const float*)d_in[0];
    const float* w_ih0     = (const float*)d_in[1];
    const float* w_hh0     = (const float*)d_in[2];
    const float* b_ih0     = (const float*)d_in[3];
    const float* b_hh0     = (const float*)d_in[4];
    const float* w_ih1     = (const float*)d_in[5];
    const float* w_hh1     = (const float*)d_in[6];
    const float* b_ih1     = (const float*)d_in[7];
    const float* b_hh1     = (const float*)d_in[8];
    const float* in_proj_w = (const float*)d_in[9];
    const float* in_proj_b = (const float*)d_in[10];
    const float* out_w     = (const float*)d_in[11];
    const float* out_b     = (const float*)d_in[12];
    const float* ln1_g     = (const float*)d_in[13];
    const float* ln1_b     = (const float*)d_in[14];
    const float* ffn_w1    = (const float*)d_in[15];
    const float* ffn_b1    = (const float*)d_in[16];
    const float* ffn_w2    = (const float*)d_in[17];
    const float* ffn_b2    = (const float*)d_in[18];
    const float* ln2_g     = (const float*)d_in[19];
    const float* ln2_b     = (const float*)d_in[20];
    const float* dec_w1    = (const float*)d_in[21];
    const float* dec_b1    = (const float*)d_in[22];
    const float* dec_w2    = (const float*)d_in[23];
    const float* dec_b2    = (const float*)d_in[24];
    const float* sc_w1     = (const float*)d_in[25];
    const float* sc_b1     = (const float*)d_in[26];
    const float* sc_w2     = (const float*)d_in[27];
    const float* sc_b2     = (const float*)d_in[28];
    float* out = (float*)d_out;

    float *ys0, *xh1, *h0, *h1, *gates, *bufA, *bufB, *bufC;
    cudaGetSymbolAddress((void**)&ys0,   g_ys0);
    cudaGetSymbolAddress((void**)&xh1,   g_xh1);
    cudaGetSymbolAddress((void**)&h0,    g_h0);
    cudaGetSymbolAddress((void**)&h1,    g_h1);
    cudaGetSymbolAddress((void**)&gates, g_gates);
    cudaGetSymbolAddress((void**)&bufA,  g_bufA);
    cudaGetSymbolAddress((void**)&bufB,  g_bufB);
    cudaGetSymbolAddress((void**)&bufC,  g_bufC);

    const int PT = 256;
    const int cellBlocks = (BD*EE + PT - 1)/PT;

    // init h,c
    zero_hc_kernel<<<cellBlocks, PT>>>();

    // -------- LSTM layer 0 (x-proj fused into cell; K=2 is trivial) --------
    for (int t = 0; t < TT; t++) {
        gemm_big(0, h0, 0, EE, w_hh0, 0, nullptr, 0, gates, 0, GG, BD, GG, EE, 1);
        lstm_cell0<<<cellBlocks, PT>>>(obs, w_ih0, b_ih0, b_hh0, t);
    }

    // -------- precompute layer-1 input projections for all timesteps -------
    gemm_big(0, ys0, 0, EE, w_ih1, 0, nullptr, 0, xh1, 0, GG, TT*BD, GG, EE, 1);

    // -------- LSTM layer 1 --------
    for (int t = 0; t < TT; t++) {
        gemm_big(0, h1, 0, EE, w_hh1, 0, nullptr, 0, gates, 0, GG, BD, GG, EE, 1);
        lstm_cell1<<<cellBlocks, PT>>>(b_ih1, b_hh1, t);
    }
    // emb == g_h1

    // -------- v projection only (softmax over size-1 axis == 1 => ctx = v) --
    // v weight rows are [512:768) of in_proj_w[m]; bias offset 512.
    gemm_big(0, h1, 0, EE,
             in_proj_w + (size_t)512*EE, (long)768*EE,
             in_proj_b + 512, 768,
             bufA, EE, MM*EE,
             BD, EE, EE, MM);

    // -------- per-mode output projection --------
    gemm_big(0, bufA, EE, MM*EE,
             out_w, (long)EE*EE,
             out_b, EE,
             bufB, EE, MM*EE,
             BD, EE, EE, MM);

    // -------- LN1 --------
    {
        dim3 g((ROWS*32 + 255)/256), b(256);
        ln_kernel<<<g,b>>>(bufB, ln1_g, ln1_b, bufA);
    }

    // -------- FFN --------
    gemm_big(1, bufA, 0, EE,   ffn_w1, 0, ffn_b1, 0, bufC, 0, 1024, ROWS, 1024, EE,   1);
    gemm_big(0, bufC, 0, 1024, ffn_w2, 0, ffn_b2, 0, bufB, 0, EE,   ROWS, EE,   1024, 1);

    // -------- LN2 -> mm_emb --------
    {
        dim3 g((ROWS*32 + 255)/256), b(256);
        ln_kernel<<<g,b>>>(bufB, ln2_g, ln2_b, bufA);
    }

    // -------- decoder head --------
    gemm_big(2, bufA, 0, EE, dec_w1, 0, dec_b1, 0, bufC, 0, 512, ROWS, 512, EE, 1);
    {   // narrow GEMM: N=24, K=512, write deltas directly into d_out
        dim3 g(1, ROWS/128, 1), b(256);
        gemm_nt<128,32,8,8,2,0><<<g,b>>>(bufC, 0, 512, dec_w2, 0, dec_b2, 0,
                                         out, 0, 24, ROWS, 24, 512);
    }
    {
        dim3 g((PRED_ELEMS + 255)/256), b(256);
        add_lastpos<<<g,b>>>(out, obs);
    }

    // -------- score head --------
    gemm_big(2, bufA, 0, EE, sc_w1, 0, sc_b1, 0, bufB, 0, 128, ROWS, 128, EE, 1);
    {
        dim3 g((ROWS*32 + 255)/256), b(256);
        sc2_kernel<<<g,b>>>(bufB, sc_w2, sc_b2, out + PRED_ELEMS);
    }
}

// round 6
// speedup vs baseline: 1.7172x; 1.7172x over previous
#include <cuda_runtime.h>
#include <cstdint>
#include <math.h>

// Problem dims
#define BD   8192
#define TT   8
#define EE   256
#define GG   1024          // 4*E
#define MM   20
#define ROWS (BD*MM)       // 163840
#define FSX  12
#define PRED_ELEMS (BD*MM*FSX*2)   // 3932160

// ---------------- scratch (static device globals; no allocation) -------------
__device__ float g_ys0[(size_t)TT*BD*EE];
__device__ float g_xh1[(size_t)TT*BD*GG];
__device__ float g_h0[BD*EE];
__device__ float g_c0[BD*EE];
__device__ float g_h1[BD*EE];
__device__ float g_c1[BD*EE];
__device__ float g_gates[(size_t)BD*GG];
__device__ float g_bufA[(size_t)ROWS*EE];
__device__ float g_bufB[(size_t)ROWS*EE];
__device__ float g_bufC[(size_t)ROWS*1024];

// ======================= tf32 mma.sync GEMM =================================
// C[r,n] = act( sum_k A[r,k]*W[n,k] + bias[n] )
// A fp32 row-major (lda), W fp32 [N,K] row-major (i.e. col-major k x n).
// CTA tile 128x128x32, 8 warps (4M x 2N), warp tile 32x64.
// smem holds tiles in FRAGMENT-MAJOR layout so fragment loads are LDS.128/LDS.64.

__device__ __forceinline__ uint32_t to_tf32(float x) {
    uint32_t r;
    asm("cvt.rna.tf32.f32 %0, %1;" : "=r"(r) : "f"(x));
    return r;
}

__device__ __forceinline__ void mma_tf32_16x8x8(float* d, const uint32_t* a, uint32_t b0, uint32_t b1) {
    asm volatile(
        "mma.sync.aligned.m16n8k8.row.col.f32.tf32.tf32.f32 "
        "{%0,%1,%2,%3}, {%4,%5,%6,%7}, {%8,%9}, {%0,%1,%2,%3};"
        : "+f"(d[0]), "+f"(d[1]), "+f"(d[2]), "+f"(d[3])
        : "r"(a[0]), "r"(a[1]), "r"(a[2]), "r"(a[3]), "r"(b0), "r"(b1));
}

// smem per buffer: A 4096 floats (16KB) + B 4096 floats (16KB); x2 buffers = 64KB
#define GEMM_SMEM 65536

template<int ACT>
__global__ void __launch_bounds__(256, 1)
mma_gemm(const float* __restrict__ A, long sA, int lda,
         const float* __restrict__ W, long sW,
         const float* __restrict__ bias, long sBias,
         float* __restrict__ C, long sC, int ldc,
         int Nreal, int K)
{
    extern __shared__ uint32_t sm[];
    uint32_t* Asm[2] = { sm,        sm + 8192 };
    uint32_t* Bsm[2] = { sm + 4096, sm + 12288 };

    const int tid  = threadIdx.x;
    const int lane = tid & 31, wid = tid >> 5;
    const int wm = wid >> 1, wn = wid & 1;        // 4 M-warps x 2 N-warps
    const int gq = lane >> 2, ctg = lane & 3;

    const float* Ab = A + (size_t)blockIdx.z * sA;
    const float* Wb = W + (size_t)blockIdx.z * sW;
    const size_t row0 = (size_t)blockIdx.y * 128;
    const int    n0   = blockIdx.x * 128;

    const int nk = K >> 5;

    float acc[2][8][4];
#pragma unroll
    for (int i = 0; i < 2; i++)
#pragma unroll
        for (int j = 0; j < 8; j++)
#pragma unroll
            for (int q = 0; q < 4; q++) acc[i][j][q] = 0.f;

    uint32_t ua[4][4], ub[4][4];

    // ---- stage loaders: global -> regs (with tf32 rounding) ----
    auto ldA = [&](int kt) {
#pragma unroll
        for (int i = 0; i < 4; i++) {
            int f = (i << 8) + tid;          // 0..1023 float4 slots
            int r = f >> 3, q = f & 7;
            float4 v = *(const float4*)(Ab + (row0 + r) * (size_t)lda + kt + (q << 2));
            ua[i][0] = to_tf32(v.x); ua[i][1] = to_tf32(v.y);
            ua[i][2] = to_tf32(v.z); ua[i][3] = to_tf32(v.w);
        }
    };
    auto ldB = [&](int kt) {
#pragma unroll
        for (int i = 0; i < 4; i++) {
            int f = (i << 8) + tid;
            int n = f >> 3, q = f & 7;
            float4 v = make_float4(0.f, 0.f, 0.f, 0.f);
            if (n0 + n < Nreal)
                v = *(const float4*)(Wb + (size_t)(n0 + n) * K + kt + (q << 2));
            ub[i][0] = to_tf32(v.x); ub[i][1] = to_tf32(v.y);
            ub[i][2] = to_tf32(v.z); ub[i][3] = to_tf32(v.w);
        }
    };
    // ---- regs -> fragment-major smem ----
    // A elem (mt,ks,lane=4g+c,reg): idx = (mt*4+ks)*128 + 16g + 4c + reg
    //   reg = hi + 2*c4  (hi = row bit3, c4 = (k&7)>>2)
    auto stA = [&](uint32_t* buf) {
#pragma unroll
        for (int i = 0; i < 4; i++) {
            int f = (i << 8) + tid;
            int r = f >> 3, q = f & 7;
            int mt = r >> 4, r8 = r & 15, g8 = r8 & 7, hi = r8 >> 3;
            int ks = q >> 1, c4 = q & 1;
            int base = ((mt << 2) + ks) * 128 + (g8 << 4) + hi + (c4 << 1);
            buf[base +  0] = ua[i][0];
            buf[base +  4] = ua[i][1];
            buf[base +  8] = ua[i][2];
            buf[base + 12] = ua[i][3];
        }
    };
    // B elem (nt,ks,lane=4g+c,slot): idx = (nt*4+ks)*64 + 8g + 2c + s
    auto stB = [&](uint32_t* buf) {
#pragma unroll
        for (int i = 0; i < 4; i++) {
            int f = (i << 8) + tid;
            int n = f >> 3, q = f & 7;
            int nt = n >> 3, g8 = n & 7;
            int ks = q >> 1, s = q & 1;
            int base = ((nt << 2) + ks) * 64 + (g8 << 3) + s;
            buf[base + 0] = ub[i][0];
            buf[base + 2] = ub[i][1];
            buf[base + 4] = ub[i][2];
            buf[base + 6] = ub[i][3];
        }
    };

    // prologue: tile 0
    ldA(0); ldB(0);
    stA(Asm[0]); stB(Bsm[0]);
    __syncthreads();

    for (int kc = 0; kc < nk; kc++) {
        const int cur = kc & 1;
        if (kc + 1 < nk) { ldA((kc + 1) << 5); ldB((kc + 1) << 5); }

        const uint32_t* Ac = Asm[cur];
        const uint32_t* Bc = Bsm[cur];
#pragma unroll
        for (int ks = 0; ks < 4; ks++) {
            uint32_t af[2][4];
#pragma unroll
            for (int mtl = 0; mtl < 2; mtl++) {
                int mt = wm * 2 + mtl;
                uint4 t = *(const uint4*)(Ac + (((mt << 2) + ks) * 32 + lane) * 4);
                af[mtl][0] = t.x; af[mtl][1] = t.y; af[mtl][2] = t.z; af[mtl][3] = t.w;
            }
#pragma unroll
            for (int ntl = 0; ntl < 8; ntl++) {
                int nt = wn * 8 + ntl;
                uint2 bt = *(const uint2*)(Bc + (((nt << 2) + ks) * 32 + lane) * 2);
                mma_tf32_16x8x8(acc[0][ntl], af[0], bt.x, bt.y);
                mma_tf32_16x8x8(acc[1][ntl], af[1], bt.x, bt.y);
            }
        }

        if (kc + 1 < nk) {
            stA(Asm[cur ^ 1]); stB(Bsm[cur ^ 1]);
            __syncthreads();
        }
    }

    // ---- epilogue: bias + activation, float2 stores ----
    const float* brow = bias ? bias + (size_t)blockIdx.z * sBias : nullptr;
    float* Cb = C + (size_t)blockIdx.z * sC;
#pragma unroll
    for (int mtl = 0; mtl < 2; mtl++) {
        size_t rA = row0 + wm * 32 + mtl * 16 + gq;
#pragma unroll
        for (int ntl = 0; ntl < 8; ntl++) {
            int col = n0 + wn * 64 + ntl * 8 + 2 * ctg;
            if (col >= Nreal) continue;
            float b0v = 0.f, b1v = 0.f;
            if (brow) { b0v = __ldg(brow + col); b1v = __ldg(brow + col + 1); }
            float v0 = acc[mtl][ntl][0] + b0v;
            float v1 = acc[mtl][ntl][1] + b1v;
            float v2 = acc[mtl][ntl][2] + b0v;
            float v3 = acc[mtl][ntl][3] + b1v;
            if (ACT == 1) {
                v0 = v0 > 0.f ? v0 : 0.f; v1 = v1 > 0.f ? v1 : 0.f;
                v2 = v2 > 0.f ? v2 : 0.f; v3 = v3 > 0.f ? v3 : 0.f;
            }
            if (ACT == 2) {
                v0 = v0 > 0.f ? v0 : expm1f(v0); v1 = v1 > 0.f ? v1 : expm1f(v1);
                v2 = v2 > 0.f ? v2 : expm1f(v2); v3 = v3 > 0.f ? v3 : expm1f(v3);
            }
            *(float2*)(Cb + rA * (size_t)ldc + col)       = make_float2(v0, v1);
            *(float2*)(Cb + (rA + 8) * (size_t)ldc + col) = make_float2(v2, v3);
        }
    }
}

// ---------------- pointwise / small kernels ---------------------------------
__device__ __forceinline__ float sigf(float x) { return 1.f / (1.f + expf(-x)); }

__global__ void zero_hc_kernel()
{
    int i = blockIdx.x * blockDim.x + threadIdx.x;
    if (i < BD * EE) { g_h0[i] = 0.f; g_c0[i] = 0.f; g_h1[i] = 0.f; g_c1[i] = 0.f; }
}

__global__ void lstm_cell0(const float* __restrict__ obs, const float* __restrict__ w_ih,
                           const float* __restrict__ b_ih, const float* __restrict__ b_hh, int t)
{
    int idx = blockIdx.x * blockDim.x + threadIdx.x;
    if (idx >= BD * EE) return;
    int b = idx >> 8, e = idx & 255;
    float x0 = obs[((long)b * TT + t) * 2 + 0];
    float x1 = obs[((long)b * TT + t) * 2 + 1];
    float gv[4];
#pragma unroll
    for (int q = 0; q < 4; q++) {
        int j = q * EE + e;
        gv[q] = g_gates[(long)b * GG + j] + x0 * w_ih[2 * j] + x1 * w_ih[2 * j + 1] + b_ih[j] + b_hh[j];
    }
    float ig = sigf(gv[0]), fg = sigf(gv[1]), gg = tanhf(gv[2]), og = sigf(gv[3]);
    float cn = fg * g_c0[idx] + ig * gg;
    float hn = og * tanhf(cn);
    g_c0[idx] = cn; g_h0[idx] = hn;
    g_ys0[(size_t)t * BD * EE + idx] = hn;
}

__global__ void lstm_cell1(const float* __restrict__ b_ih, const float* __restrict__ b_hh, int t)
{
    int idx = blockIdx.x * blockDim.x + threadIdx.x;
    if (idx >= BD * EE) return;
    int b = idx >> 8, e = idx & 255;
    const size_t xbase = ((size_t)t * BD + b) * GG;
    float gv[4];
#pragma unroll
    for (int q = 0; q < 4; q++) {
        int j = q * EE + e;
        gv[q] = g_gates[(long)b * GG + j] + g_xh1[xbase + j] + b_ih[j] + b_hh[j];
    }
    float ig = sigf(gv[0]), fg = sigf(gv[1]), gg = tanhf(gv[2]), og = sigf(gv[3]);
    float cn = fg * g_c1[idx] + ig * gg;
    float hn = og * tanhf(cn);
    g_c1[idx] = cn; g_h1[idx] = hn;
}

__global__ void ln_kernel(const float* __restrict__ x, const float* __restrict__ gam,
                          const float* __restrict__ bet, float* __restrict__ y)
{
    size_t warp = ((size_t)blockIdx.x * blockDim.x + threadIdx.x) >> 5;
    int lane = threadIdx.x & 31;
    if (warp >= (size_t)ROWS) return;
    const float* xr = x + warp * EE;
    float4 p0 = *(const float4*)(xr + lane * 8);
    float4 p1 = *(const float4*)(xr + lane * 8 + 4);
    float v[8] = {p0.x, p0.y, p0.z, p0.w, p1.x, p1.y, p1.z, p1.w};
    float s = 0.f, sq = 0.f;
#pragma unroll
    for (int i = 0; i < 8; i++) { s += v[i]; sq += v[i] * v[i]; }
#pragma unroll
    for (int o = 16; o; o >>= 1) {
        s  += __shfl_xor_sync(0xffffffffu, s,  o);
        sq += __shfl_xor_sync(0xffffffffu, sq, o);
    }
    float m   = s * (1.f / EE);
    float var = sq * (1.f / EE) - m * m;
    float inv = rsqrtf(var + 1e-5f);
    float* yr = y + warp * EE;
#pragma unroll
    for (int i = 0; i < 8; i++) {
        int e = lane * 8 + i;
        yr[e] = (v[i] - m) * inv * gam[e] + bet[e];
    }
}

__global__ void add_lastpos(float* __restrict__ pred, const float* __restrict__ obs)
{
    size_t idx = (size_t)blockIdx.x * blockDim.x + threadIdx.x;
    if (idx >= (size_t)PRED_ELEMS) return;
    size_t b = idx / (MM * FSX * 2);
    int c = (int)(idx & 1);
    pred[idx] += obs[(b * TT + (TT - 1)) * 2 + c];
}

__global__ void sc2_kernel(const float* __restrict__ s, const float* __restrict__ w,
                           const float* __restrict__ b2, float* __restrict__ outp)
{
    size_t gwarp = ((size_t)blockIdx.x * blockDim.x + threadIdx.x) >> 5;
    int lane = threadIdx.x & 31;
    if (gwarp >= (size_t)ROWS) return;
    const float* row = s + gwarp * 128;
    float4 a  = *(const float4*)(row + lane * 4);
    float4 ww = *(const float4*)(w   + lane * 4);
    float acc = a.x * ww.x + a.y * ww.y + a.z * ww.z + a.w * ww.w;
#pragma unroll
    for (int o = 16; o; o >>= 1) acc += __shfl_xor_sync(0xffffffffu, acc, o);
    if (lane == 0) outp[gwarp] = acc + b2[0];
}

// ---------------- host-side -------------------------------------------------
static void tcgemm(int act,
                   const float* A, long sA, int lda,
                   const float* W, long sW,
                   const float* bias, long sBias,
                   float* C, long sC, int ldc,
                   int Mrows, int N, int K, int nb)
{
    static bool attr_done = false;
    if (!attr_done) {
        cudaFuncSetAttribute(mma_gemm<0>, cudaFuncAttributeMaxDynamicSharedMemorySize, GEMM_SMEM);
        cudaFuncSetAttribute(mma_gemm<1>, cudaFuncAttributeMaxDynamicSharedMemorySize, GEMM_SMEM);
        cudaFuncSetAttribute(mma_gemm<2>, cudaFuncAttributeMaxDynamicSharedMemorySize, GEMM_SMEM);
        attr_done = true;
    }
    dim3 g((N + 127) / 128, Mrows / 128, nb), b(256);
    switch (act) {
    case 0: mma_gemm<0><<<g, b, GEMM_SMEM>>>(A, sA, lda, W, sW, bias, sBias, C, sC, ldc, N, K); break;
    case 1: mma_gemm<1><<<g, b, GEMM_SMEM>>>(A, sA, lda, W, sW, bias, sBias, C, sC, ldc, N, K); break;
    default: mma_gemm<2><<<g, b, GEMM_SMEM>>>(A, sA, lda, W, sW, bias, sBias, C, sC, ldc, N, K); break;
    }
}

extern "C" void kernel_launch(void* const* d_in, const int* in_sizes, int n_in,
                              void* d_out, int out_size)
{
    (void)in_sizes; (void)n_in; (void)out_size;
    const float* obs       = (const float*)d_in[0];
    const float* w_ih0     = (const float*)d_in[1];
    const float* w_hh0     = (const float*)d_in[2];
    const float* b_ih0     = (const float*)d_in[3];
    const float* b_hh0     = (const float*)d_in[4];
    const float* w_ih1     = (const float*)d_in[5];
    const float* w_hh1     = (const float*)d_in[6];
    const float* b_ih1     = (const float*)d_in[7];
    const float* b_hh1     = (const float*)d_in[8];
    const float* in_proj_w = (const float*)d_in[9];
    const float* in_proj_b = (const float*)d_in[10];
    const float* out_w     = (const float*)d_in[11];
    const float* out_b     = (const float*)d_in[12];
    const float* ln1_g     = (const float*)d_in[13];
    const float* ln1_b     = (const float*)d_in[14];
    const float* ffn_w1    = (const float*)d_in[15];
    const float* ffn_b1    = (const float*)d_in[16];
    const float* ffn_w2    = (const float*)d_in[17];
    const float* ffn_b2    = (const float*)d_in[18];
    const float* ln2_g     = (const float*)d_in[19];
    const float* ln2_b     = (const float*)d_in[20];
    const float* dec_w1    = (const float*)d_in[21];
    const float* dec_b1    = (const float*)d_in[22];
    const float* dec_w2    = (const float*)d_in[23];
    const float* dec_b2    = (const float*)d_in[24];
    const float* sc_w1     = (const float*)d_in[25];
    const float* sc_b1     = (const float*)d_in[26];
    const float* sc_w2     = (const float*)d_in[27];
    const float* sc_b2     = (const float*)d_in[28];
    float* out = (float*)d_out;

    float *ys0, *xh1, *h0, *h1, *gates, *bufA, *bufB, *bufC;
    cudaGetSymbolAddress((void**)&ys0,   g_ys0);
    cudaGetSymbolAddress((void**)&xh1,   g_xh1);
    cudaGetSymbolAddress((void**)&h0,    g_h0);
    cudaGetSymbolAddress((void**)&h1,    g_h1);
    cudaGetSymbolAddress((void**)&gates, g_gates);
    cudaGetSymbolAddress((void**)&bufA,  g_bufA);
    cudaGetSymbolAddress((void**)&bufB,  g_bufB);
    cudaGetSymbolAddress((void**)&bufC,  g_bufC);

    const int PT = 256;
    const int cellBlocks = (BD * EE + PT - 1) / PT;

    zero_hc_kernel<<<cellBlocks, PT>>>();

    // -------- LSTM layer 0 (x-proj fused into cell; K=2 trivial) --------
    for (int t = 0; t < TT; t++) {
        tcgemm(0, h0, 0, EE, w_hh0, 0, nullptr, 0, gates, 0, GG, BD, GG, EE, 1);
        lstm_cell0<<<cellBlocks, PT>>>(obs, w_ih0, b_ih0, b_hh0, t);
    }

    // -------- layer-1 input projections (all timesteps at once) --------
    tcgemm(0, ys0, 0, EE, w_ih1, 0, nullptr, 0, xh1, 0, GG, TT * BD, GG, EE, 1);

    // -------- LSTM layer 1 --------
    for (int t = 0; t < TT; t++) {
        tcgemm(0, h1, 0, EE, w_hh1, 0, nullptr, 0, gates, 0, GG, BD, GG, EE, 1);
        lstm_cell1<<<cellBlocks, PT>>>(b_ih1, b_hh1, t);
    }

    // -------- v projection (softmax over size-1 axis == 1 => ctx = v) --------
    tcgemm(0, h1, 0, EE,
           in_proj_w + (size_t)512 * EE, (long)768 * EE,
           in_proj_b + 512, 768,
           bufA, EE, MM * EE,
           BD, EE, EE, MM);

    // -------- per-mode output projection --------
    tcgemm(0, bufA, EE, MM * EE,
           out_w, (long)EE * EE,
           out_b, EE,
           bufB, EE, MM * EE,
           BD, EE, EE, MM);

    // -------- LN1 --------
    {
        dim3 g((ROWS * 32 + 255) / 256), b(256);
        ln_kernel<<<g, b>>>(bufB, ln1_g, ln1_b, bufA);
    }

    // -------- FFN --------
    tcgemm(1, bufA, 0, EE,   ffn_w1, 0, ffn_b1, 0, bufC, 0, 1024, ROWS, 1024, EE,   1);
    tcgemm(0, bufC, 0, 1024, ffn_w2, 0, ffn_b2, 0, bufB, 0, EE,   ROWS, EE,   1024, 1);

    // -------- LN2 -> mm_emb --------
    {
        dim3 g((ROWS * 32 + 255) / 256), b(256);
        ln_kernel<<<g, b>>>(bufB, ln2_g, ln2_b, bufA);
    }

    // -------- decoder head --------
    tcgemm(2, bufA, 0, EE, dec_w1, 0, dec_b1, 0, bufC, 0, 512, ROWS, 512, EE, 1);
    tcgemm(0, bufC, 0, 512, dec_w2, 0, dec_b2, 0, out, 0, 24, ROWS, 24, 512, 1);
    {
        dim3 g((PRED_ELEMS + 255) / 256), b(256);
        add_lastpos<<<g, b>>>(out, obs);
    }

    // -------- score head --------
    tcgemm(2, bufA, 0, EE, sc_w1, 0, sc_b1, 0, bufB, 0, 128, ROWS, 128, EE, 1);
    {
        dim3 g((ROWS * 32 + 255) / 256), b(256);
        sc2_kernel<<<g, b>>>(bufB, sc_w2, sc_b2, out + PRED_ELEMS);
    }
}

// round 7
// speedup vs baseline: 1.7713x; 1.0315x over previous
#include <cuda_runtime.h>
#include <cstdint>
#include <math.h>

// Problem dims
#define BD   8192
#define TT   8
#define EE   256
#define GG   1024          // 4*E
#define MM   20
#define ROWS (BD*MM)       // 163840
#define FSX  12
#define PRED_ELEMS (BD*MM*FSX*2)   // 3932160

// ---------------- scratch (static device globals; no allocation) -------------
__device__ float g_ys0[(size_t)TT*BD*EE];
__device__ float g_xh1[(size_t)TT*BD*GG];
__device__ float g_h0[BD*EE];
__device__ float g_c0[BD*EE];
__device__ float g_h1[BD*EE];
__device__ float g_c1[BD*EE];
__device__ float g_gates[(size_t)BD*GG];
__device__ float g_bufA[(size_t)ROWS*EE];
__device__ float g_bufB[(size_t)ROWS*EE];
__device__ float g_bufC[(size_t)ROWS*1024];

// ======================= tf32 mma.sync GEMM =================================
// C[r,n] = act( sum_k A[r,k]*W[n,k] + bias[n] )
// A fp32 row-major (lda), W fp32 [N,K] row-major.
// CTA tile 128x64x32, 8 warps (4M x 2N), warp tile 32x32, 2 CTAs/SM.
// smem tiles in FRAGMENT-MAJOR layout: A fragments load as LDS.128, B as LDS.64.

__device__ __forceinline__ uint32_t to_tf32(float x) {
    uint32_t r;
    asm("cvt.rna.tf32.f32 %0, %1;" : "=r"(r) : "f"(x));
    return r;
}

__device__ __forceinline__ void mma_tf32_16x8x8(float* d, const uint32_t* a, uint32_t b0, uint32_t b1) {
    asm volatile(
        "mma.sync.aligned.m16n8k8.row.col.f32.tf32.tf32.f32 "
        "{%0,%1,%2,%3}, {%4,%5,%6,%7}, {%8,%9}, {%0,%1,%2,%3};"
        : "+f"(d[0]), "+f"(d[1]), "+f"(d[2]), "+f"(d[3])
        : "r"(a[0]), "r"(a[1]), "r"(a[2]), "r"(a[3]), "r"(b0), "r"(b1));
}

// smem per buffer: A 4096 u32 (16KB) + B 2048 u32 (8KB); x2 buffers = 48KB
#define GEMM_SMEM 49152

template<int ACT>
__global__ void __launch_bounds__(256, 2)
mma_gemm(const float* __restrict__ A, long sA, int lda,
         const float* __restrict__ W, long sW,
         const float* __restrict__ bias, long sBias,
         float* __restrict__ C, long sC, int ldc,
         int Nreal, int K)
{
    extern __shared__ uint32_t sm[];
    uint32_t* Asm[2] = { sm,        sm + 6144 };
    uint32_t* Bsm[2] = { sm + 4096, sm + 10240 };

    const int tid  = threadIdx.x;
    const int lane = tid & 31, wid = tid >> 5;
    const int wm = wid >> 1, wn = wid & 1;        // 4 M-warps x 2 N-warps
    const int gq = lane >> 2, ctg = lane & 3;

    const float* Ab = A + (size_t)blockIdx.z * sA;
    const float* Wb = W + (size_t)blockIdx.z * sW;
    const size_t row0 = (size_t)blockIdx.y * 128;
    const int    n0   = blockIdx.x * 64;

    const int nk = K >> 5;

    float acc[2][4][4];
#pragma unroll
    for (int i = 0; i < 2; i++)
#pragma unroll
        for (int j = 0; j < 4; j++)
#pragma unroll
            for (int q = 0; q < 4; q++) acc[i][j][q] = 0.f;

    uint32_t ua[4][4], ub[2][4];

    // ---- stage loaders: global -> regs (with tf32 rounding) ----
    auto ldA = [&](int kt) {
#pragma unroll
        for (int i = 0; i < 4; i++) {
            int f = (i << 8) + tid;          // 0..1023 float4 slots (128 rows x 8)
            int r = f >> 3, q = f & 7;
            float4 v = *(const float4*)(Ab + (row0 + r) * (size_t)lda + kt + (q << 2));
            ua[i][0] = to_tf32(v.x); ua[i][1] = to_tf32(v.y);
            ua[i][2] = to_tf32(v.z); ua[i][3] = to_tf32(v.w);
        }
    };
    auto ldB = [&](int kt) {
#pragma unroll
        for (int i = 0; i < 2; i++) {
            int f = (i << 8) + tid;          // 0..511 float4 slots (64 rows x 8)
            int n = f >> 3, q = f & 7;
            float4 v = make_float4(0.f, 0.f, 0.f, 0.f);
            if (n0 + n < Nreal)
                v = *(const float4*)(Wb + (size_t)(n0 + n) * K + kt + (q << 2));
            ub[i][0] = to_tf32(v.x); ub[i][1] = to_tf32(v.y);
            ub[i][2] = to_tf32(v.z); ub[i][3] = to_tf32(v.w);
        }
    };
    // ---- regs -> fragment-major smem ----
    auto stA = [&](uint32_t* buf) {
#pragma unroll
        for (int i = 0; i < 4; i++) {
            int f = (i << 8) + tid;
            int r = f >> 3, q = f & 7;
            int mt = r >> 4, r8 = r & 15, g8 = r8 & 7, hi = r8 >> 3;
            int ks = q >> 1, c4 = q & 1;
            int base = ((mt << 2) + ks) * 128 + (g8 << 4) + hi + (c4 << 1);
            buf[base +  0] = ua[i][0];
            buf[base +  4] = ua[i][1];
            buf[base +  8] = ua[i][2];
            buf[base + 12] = ua[i][3];
        }
    };
    auto stB = [&](uint32_t* buf) {
#pragma unroll
        for (int i = 0; i < 2; i++) {
            int f = (i << 8) + tid;
            int n = f >> 3, q = f & 7;
            int nt = n >> 3, g8 = n & 7;
            int ks = q >> 1, s = q & 1;
            int base = ((nt << 2) + ks) * 64 + (g8 << 3) + s;
            buf[base + 0] = ub[i][0];
            buf[base + 2] = ub[i][1];
            buf[base + 4] = ub[i][2];
            buf[base + 6] = ub[i][3];
        }
    };

    // prologue: tile 0
    ldA(0); ldB(0);
    stA(Asm[0]); stB(Bsm[0]);
    __syncthreads();

    for (int kc = 0; kc < nk; kc++) {
        const int cur = kc & 1;
        if (kc + 1 < nk) { ldA((kc + 1) << 5); ldB((kc + 1) << 5); }

        const uint32_t* Ac = Asm[cur];
        const uint32_t* Bc = Bsm[cur];
#pragma unroll
        for (int ks = 0; ks < 4; ks++) {
            uint32_t af[2][4];
#pragma unroll
            for (int mtl = 0; mtl < 2; mtl++) {
                int mt = wm * 2 + mtl;
                uint4 t = *(const uint4*)(Ac + (((mt << 2) + ks) * 32 + lane) * 4);
                af[mtl][0] = t.x; af[mtl][1] = t.y; af[mtl][2] = t.z; af[mtl][3] = t.w;
            }
#pragma unroll
            for (int ntl = 0; ntl < 4; ntl++) {
                int nt = wn * 4 + ntl;
                uint2 bt = *(const uint2*)(Bc + (((nt << 2) + ks) * 32 + lane) * 2);
                mma_tf32_16x8x8(acc[0][ntl], af[0], bt.x, bt.y);
                mma_tf32_16x8x8(acc[1][ntl], af[1], bt.x, bt.y);
            }
        }

        if (kc + 1 < nk) {
            stA(Asm[cur ^ 1]); stB(Bsm[cur ^ 1]);
            __syncthreads();
        }
    }

    // ---- epilogue: bias + activation, float2 stores ----
    const float* brow = bias ? bias + (size_t)blockIdx.z * sBias : nullptr;
    float* Cb = C + (size_t)blockIdx.z * sC;
#pragma unroll
    for (int mtl = 0; mtl < 2; mtl++) {
        size_t rA = row0 + wm * 32 + mtl * 16 + gq;
#pragma unroll
        for (int ntl = 0; ntl < 4; ntl++) {
            int col = n0 + wn * 32 + ntl * 8 + 2 * ctg;
            if (col >= Nreal) continue;
            float b0v = 0.f, b1v = 0.f;
            if (brow) { b0v = __ldg(brow + col); b1v = __ldg(brow + col + 1); }
            float v0 = acc[mtl][ntl][0] + b0v;
            float v1 = acc[mtl][ntl][1] + b1v;
            float v2 = acc[mtl][ntl][2] + b0v;
            float v3 = acc[mtl][ntl][3] + b1v;
            if (ACT == 1) {
                v0 = v0 > 0.f ? v0 : 0.f; v1 = v1 > 0.f ? v1 : 0.f;
                v2 = v2 > 0.f ? v2 : 0.f; v3 = v3 > 0.f ? v3 : 0.f;
            }
            if (ACT == 2) {
                v0 = v0 > 0.f ? v0 : expm1f(v0); v1 = v1 > 0.f ? v1 : expm1f(v1);
                v2 = v2 > 0.f ? v2 : expm1f(v2); v3 = v3 > 0.f ? v3 : expm1f(v3);
            }
            *(float2*)(Cb + rA * (size_t)ldc + col)       = make_float2(v0, v1);
            *(float2*)(Cb + (rA + 8) * (size_t)ldc + col) = make_float2(v2, v3);
        }
    }
}

// ---------------- pointwise / small kernels ---------------------------------
__device__ __forceinline__ float sigf(float x) { return 1.f / (1.f + expf(-x)); }

__global__ void zero_hc_kernel()
{
    int i = blockIdx.x * blockDim.x + threadIdx.x;
    if (i < BD * EE) { g_h0[i] = 0.f; g_c0[i] = 0.f; g_h1[i] = 0.f; g_c1[i] = 0.f; }
}

__global__ void lstm_cell0(const float* __restrict__ obs, const float* __restrict__ w_ih,
                           const float* __restrict__ b_ih, const float* __restrict__ b_hh, int t)
{
    int idx = blockIdx.x * blockDim.x + threadIdx.x;
    if (idx >= BD * EE) return;
    int b = idx >> 8, e = idx & 255;
    float x0 = obs[((long)b * TT + t) * 2 + 0];
    float x1 = obs[((long)b * TT + t) * 2 + 1];
    float gv[4];
#pragma unroll
    for (int q = 0; q < 4; q++) {
        int j = q * EE + e;
        gv[q] = g_gates[(long)b * GG + j] + x0 * w_ih[2 * j] + x1 * w_ih[2 * j + 1] + b_ih[j] + b_hh[j];
    }
    float ig = sigf(gv[0]), fg = sigf(gv[1]), gg = tanhf(gv[2]), og = sigf(gv[3]);
    float cn = fg * g_c0[idx] + ig * gg;
    float hn = og * tanhf(cn);
    g_c0[idx] = cn; g_h0[idx] = hn;
    g_ys0[(size_t)t * BD * EE + idx] = hn;
}

__global__ void lstm_cell1(const float* __restrict__ b_ih, const float* __restrict__ b_hh, int t)
{
    int idx = blockIdx.x * blockDim.x + threadIdx.x;
    if (idx >= BD * EE) return;
    int b = idx >> 8, e = idx & 255;
    const size_t xbase = ((size_t)t * BD + b) * GG;
    float gv[4];
#pragma unroll
    for (int q = 0; q < 4; q++) {
        int j = q * EE + e;
        gv[q] = g_gates[(long)b * GG + j] + g_xh1[xbase + j] + b_ih[j] + b_hh[j];
    }
    float ig = sigf(gv[0]), fg = sigf(gv[1]), gg = tanhf(gv[2]), og = sigf(gv[3]);
    float cn = fg * g_c1[idx] + ig * gg;
    float hn = og * tanhf(cn);
    g_c1[idx] = cn; g_h1[idx] = hn;
}

__global__ void ln_kernel(const float* __restrict__ x, const float* __restrict__ gam,
                          const float* __restrict__ bet, float* __restrict__ y)
{
    size_t warp = ((size_t)blockIdx.x * blockDim.x + threadIdx.x) >> 5;
    int lane = threadIdx.x & 31;
    if (warp >= (size_t)ROWS) return;
    const float* xr = x + warp * EE;
    float4 p0 = *(const float4*)(xr + lane * 8);
    float4 p1 = *(const float4*)(xr + lane * 8 + 4);
    float v[8] = {p0.x, p0.y, p0.z, p0.w, p1.x, p1.y, p1.z, p1.w};
    float s = 0.f, sq = 0.f;
#pragma unroll
    for (int i = 0; i < 8; i++) { s += v[i]; sq += v[i] * v[i]; }
#pragma unroll
    for (int o = 16; o; o >>= 1) {
        s  += __shfl_xor_sync(0xffffffffu, s,  o);
        sq += __shfl_xor_sync(0xffffffffu, sq, o);
    }
    float m   = s * (1.f / EE);
    float var = sq * (1.f / EE) - m * m;
    float inv = rsqrtf(var + 1e-5f);
    float* yr = y + warp * EE;
#pragma unroll
    for (int i = 0; i < 8; i++) {
        int e = lane * 8 + i;
        yr[e] = (v[i] - m) * inv * gam[e] + bet[e];
    }
}

__global__ void add_lastpos(float* __restrict__ pred, const float* __restrict__ obs)
{
    size_t idx = (size_t)blockIdx.x * blockDim.x + threadIdx.x;
    if (idx >= (size_t)PRED_ELEMS) return;
    size_t b = idx / (MM * FSX * 2);
    int c = (int)(idx & 1);
    pred[idx] += obs[(b * TT + (TT - 1)) * 2 + c];
}

__global__ void sc2_kernel(const float* __restrict__ s, const float* __restrict__ w,
                           const float* __restrict__ b2, float* __restrict__ outp)
{
    size_t gwarp = ((size_t)blockIdx.x * blockDim.x + threadIdx.x) >> 5;
    int lane = threadIdx.x & 31;
    if (gwarp >= (size_t)ROWS) return;
    const float* row = s + gwarp * 128;
    float4 a  = *(const float4*)(row + lane * 4);
    float4 ww = *(const float4*)(w   + lane * 4);
    float acc = a.x * ww.x + a.y * ww.y + a.z * ww.z + a.w * ww.w;
#pragma unroll
    for (int o = 16; o; o >>= 1) acc += __shfl_xor_sync(0xffffffffu, acc, o);
    if (lane == 0) outp[gwarp] = acc + b2[0];
}

// ---------------- host-side -------------------------------------------------
static void tcgemm(int act,
                   const float* A, long sA, int lda,
                   const float* W, long sW,
                   const float* bias, long sBias,
                   float* C, long sC, int ldc,
                   int Mrows, int N, int K, int nb)
{
    static bool attr_done = false;
    if (!attr_done) {
        cudaFuncSetAttribute(mma_gemm<0>, cudaFuncAttributeMaxDynamicSharedMemorySize, GEMM_SMEM);
        cudaFuncSetAttribute(mma_gemm<1>, cudaFuncAttributeMaxDynamicSharedMemorySize, GEMM_SMEM);
        cudaFuncSetAttribute(mma_gemm<2>, cudaFuncAttributeMaxDynamicSharedMemorySize, GEMM_SMEM);
        attr_done = true;
    }
    dim3 g((N + 63) / 64, Mrows / 128, nb), b(256);
    switch (act) {
    case 0: mma_gemm<0><<<g, b, GEMM_SMEM>>>(A, sA, lda, W, sW, bias, sBias, C, sC, ldc, N, K); break;
    case 1: mma_gemm<1><<<g, b, GEMM_SMEM>>>(A, sA, lda, W, sW, bias, sBias, C, sC, ldc, N, K); break;
    default: mma_gemm<2><<<g, b, GEMM_SMEM>>>(A, sA, lda, W, sW, bias, sBias, C, sC, ldc, N, K); break;
    }
}

extern "C" void kernel_launch(void* const* d_in, const int* in_sizes, int n_in,
                              void* d_out, int out_size)
{
    (void)in_sizes; (void)n_in; (void)out_size;
    const float* obs       = (const float*)d_in[0];
    const float* w_ih0     = (const float*)d_in[1];
    const float* w_hh0     = (const float*)d_in[2];
    const float* b_ih0     = (const float*)d_in[3];
    const float* b_hh0     = (const float*)d_in[4];
    const float* w_ih1     = (const float*)d_in[5];
    const float* w_hh1     = (const float*)d_in[6];
    const float* b_ih1     = (const float*)d_in[7];
    const float* b_hh1     = (const float*)d_in[8];
    const float* in_proj_w = (const float*)d_in[9];
    const float* in_proj_b = (const float*)d_in[10];
    const float* out_w     = (const float*)d_in[11];
    const float* out_b     = (const float*)d_in[12];
    const float* ln1_g     = (const float*)d_in[13];
    const float* ln1_b     = (const float*)d_in[14];
    const float* ffn_w1    = (const float*)d_in[15];
    const float* ffn_b1    = (const float*)d_in[16];
    const float* ffn_w2    = (const float*)d_in[17];
    const float* ffn_b2    = (const float*)d_in[18];
    const float* ln2_g     = (const float*)d_in[19];
    const float* ln2_b     = (const float*)d_in[20];
    const float* dec_w1    = (const float*)d_in[21];
    const float* dec_b1    = (const float*)d_in[22];
    const float* dec_w2    = (const float*)d_in[23];
    const float* dec_b2    = (const float*)d_in[24];
    const float* sc_w1     = (const float*)d_in[25];
    const float* sc_b1     = (const float*)d_in[26];
    const float* sc_w2     = (const float*)d_in[27];
    const float* sc_b2     = (const float*)d_in[28];
    float* out = (float*)d_out;

    float *ys0, *xh1, *h0, *h1, *gates, *bufA, *bufB, *bufC;
    cudaGetSymbolAddress((void**)&ys0,   g_ys0);
    cudaGetSymbolAddress((void**)&xh1,   g_xh1);
    cudaGetSymbolAddress((void**)&h0,    g_h0);
    cudaGetSymbolAddress((void**)&h1,    g_h1);
    cudaGetSymbolAddress((void**)&gates, g_gates);
    cudaGetSymbolAddress((void**)&bufA,  g_bufA);
    cudaGetSymbolAddress((void**)&bufB,  g_bufB);
    cudaGetSymbolAddress((void**)&bufC,  g_bufC);

    const int PT = 256;
    const int cellBlocks = (BD * EE + PT - 1) / PT;

    zero_hc_kernel<<<cellBlocks, PT>>>();

    // -------- LSTM layer 0 (x-proj fused into cell; K=2 trivial) --------
    for (int t = 0; t < TT; t++) {
        tcgemm(0, h0, 0, EE, w_hh0, 0, nullptr, 0, gates, 0, GG, BD, GG, EE, 1);
        lstm_cell0<<<cellBlocks, PT>>>(obs, w_ih0, b_ih0, b_hh0, t);
    }

    // -------- layer-1 input projections (all timesteps at once) --------
    tcgemm(0, ys0, 0, EE, w_ih1, 0, nullptr, 0, xh1, 0, GG, TT * BD, GG, EE, 1);

    // -------- LSTM layer 1 --------
    for (int t = 0; t < TT; t++) {
        tcgemm(0, h1, 0, EE, w_hh1, 0, nullptr, 0, gates, 0, GG, BD, GG, EE, 1);
        lstm_cell1<<<cellBlocks, PT>>>(b_ih1, b_hh1, t);
    }

    // -------- v projection (softmax over size-1 axis == 1 => ctx = v) --------
    tcgemm(0, h1, 0, EE,
           in_proj_w + (size_t)512 * EE, (long)768 * EE,
           in_proj_b + 512, 768,
           bufA, EE, MM * EE,
           BD, EE, EE, MM);

    // -------- per-mode output projection --------
    tcgemm(0, bufA, EE, MM * EE,
           out_w, (long)EE * EE,
           out_b, EE,
           bufB, EE, MM * EE,
           BD, EE, EE, MM);

    // -------- LN1 --------
    {
        dim3 g((ROWS * 32 + 255) / 256), b(256);
        ln_kernel<<<g, b>>>(bufB, ln1_g, ln1_b, bufA);
    }

    // -------- FFN --------
    tcgemm(1, bufA, 0, EE,   ffn_w1, 0, ffn_b1, 0, bufC, 0, 1024, ROWS, 1024, EE,   1);
    tcgemm(0, bufC, 0, 1024, ffn_w2, 0, ffn_b2, 0, bufB, 0, EE,   ROWS, EE,   1024, 1);

    // -------- LN2 -> mm_emb --------
    {
        dim3 g((ROWS * 32 + 255) / 256), b(256);
        ln_kernel<<<g, b>>>(bufB, ln2_g, ln2_b, bufA);
    }

    // -------- decoder head --------
    tcgemm(2, bufA, 0, EE, dec_w1, 0, dec_b1, 0, bufC, 0, 512, ROWS, 512, EE, 1);
    tcgemm(0, bufC, 0, 512, dec_w2, 0, dec_b2, 0, out, 0, 24, ROWS, 24, 512, 1);
    {
        dim3 g((PRED_ELEMS + 255) / 256), b(256);
        add_lastpos<<<g, b>>>(out, obs);
    }

    // -------- score head --------
    tcgemm(2, bufA, 0, EE, sc_w1, 0, sc_b1, 0, bufB, 0, 128, ROWS, 128, EE, 1);
    {
        dim3 g((ROWS * 32 + 255) / 256), b(256);
        sc2_kernel<<<g, b>>>(bufB, sc_w2, sc_b2, out + PRED_ELEMS);
    }
}

// round 8
// speedup vs baseline: 3.0789x; 1.7382x over previous
#include <cuda_runtime.h>
#include <cuda_fp16.h>
#include <cstdint>
#include <math.h>

// Problem dims
#define BD   8192
#define TT   8
#define EE   256
#define GG   1024          // 4*E
#define MM   20
#define ROWS (BD*MM)       // 163840
#define FSX  12
#define PRED_ELEMS (BD*MM*FSX*2)   // 3932160

// ---------------- scratch (static device globals; no allocation) -------------
__device__ float g_ys0[(size_t)TT*BD*EE];
__device__ float g_xh1[(size_t)TT*BD*GG];
__device__ float g_h0[BD*EE];
__device__ float g_c0[BD*EE];
__device__ float g_h1[BD*EE];
__device__ float g_c1[BD*EE];
__device__ float g_gates[(size_t)BD*GG];
__device__ float g_bufA[(size_t)ROWS*EE];
__device__ float g_bufB[(size_t)ROWS*EE];
__device__ float g_bufC[(size_t)ROWS*1024];

// ======================= fp16 mma.sync GEMM =================================
// C[r,n] = act( sum_k A[r,k]*W[n,k] + bias[n] ), fp32 in/out, fp16 MMA inputs,
// fp32 accumulate. CTA tile 128x64x64, 8 warps (4M x 2N), warp tile 32x32,
// 2 CTAs/SM. smem tiles fragment-major (A frag = LDS.128, B frag = LDS.64)
// with XOR-by-ks swizzle for conflict-free STS.

__device__ __forceinline__ uint32_t packh2(float lo, float hi) {
    __half2 h = __floats2half2_rn(lo, hi);
    return *(uint32_t*)&h;
}

__device__ __forceinline__ void mma_f16_16x8x16(float* d, const uint32_t* a, uint32_t b0, uint32_t b1) {
    asm volatile(
        "mma.sync.aligned.m16n8k16.row.col.f32.f16.f16.f32 "
        "{%0,%1,%2,%3}, {%4,%5,%6,%7}, {%8,%9}, {%0,%1,%2,%3};"
        : "+f"(d[0]), "+f"(d[1]), "+f"(d[2]), "+f"(d[3])
        : "r"(a[0]), "r"(a[1]), "r"(a[2]), "r"(a[3]), "r"(b0), "r"(b1));
}

// per buffer: A 4096 u32 (16KB, 128x64 halves) + B 2048 u32 (8KB, 64x64 halves)
// double buffered: 2 * 6144 u32 = 48KB
#define GEMM_SMEM 49152

template<int ACT>
__global__ void __launch_bounds__(256, 2)
mma_gemm(const float* __restrict__ A, long sA, int lda,
         const float* __restrict__ W, long sW,
         const float* __restrict__ bias, long sBias,
         float* __restrict__ C, long sC, int ldc,
         int Nreal, int K)
{
    extern __shared__ uint32_t sm[];
    uint32_t* Asm[2] = { sm,        sm + 6144 };
    uint32_t* Bsm[2] = { sm + 4096, sm + 10240 };

    const int tid  = threadIdx.x;
    const int lane = tid & 31, wid = tid >> 5;
    const int wm = wid >> 1, wn = wid & 1;        // 4 M-warps x 2 N-warps
    const int gq = lane >> 2, ctg = lane & 3;

    const float* Ab = A + (size_t)blockIdx.z * sA;
    const float* Wb = W + (size_t)blockIdx.z * sW;
    const size_t row0 = (size_t)blockIdx.y * 128;
    const int    n0   = blockIdx.x * 64;

    const int nk = K >> 6;                        // K-chunk = 64

    float acc[2][4][4];
#pragma unroll
    for (int i = 0; i < 2; i++)
#pragma unroll
        for (int j = 0; j < 4; j++)
#pragma unroll
            for (int q = 0; q < 4; q++) acc[i][j][q] = 0.f;

    uint32_t ua[4][4], ub[2][4];

    // ---- stage loaders: global -> regs (fp32 -> fp16x2) ----
    // A: slot f = i*256+tid -> row = f>>3 (0..127), k8 = f&7 (8 halves each)
    auto ldA = [&](int kt) {
#pragma unroll
        for (int i = 0; i < 4; i++) {
            int r  = (i << 5) + (tid >> 3);
            int k0 = (tid & 7) << 3;
            const float* p = Ab + (row0 + r) * (size_t)lda + kt + k0;
            float4 v0 = *(const float4*)(p);
            float4 v1 = *(const float4*)(p + 4);
            ua[i][0] = packh2(v0.x, v0.y); ua[i][1] = packh2(v0.z, v0.w);
            ua[i][2] = packh2(v1.x, v1.y); ua[i][3] = packh2(v1.z, v1.w);
        }
    };
    auto ldB = [&](int kt) {
#pragma unroll
        for (int i = 0; i < 2; i++) {
            int n  = (i << 5) + (tid >> 3);
            int k0 = (tid & 7) << 3;
            float4 v0 = make_float4(0.f,0.f,0.f,0.f), v1 = v0;
            if (n0 + n < Nreal) {
                const float* p = Wb + (size_t)(n0 + n) * K + kt + k0;
                v0 = *(const float4*)(p);
                v1 = *(const float4*)(p + 4);
            }
            ub[i][0] = packh2(v0.x, v0.y); ub[i][1] = packh2(v0.z, v0.w);
            ub[i][2] = packh2(v1.x, v1.y); ub[i][3] = packh2(v1.z, v1.w);
        }
    };
    // ---- regs -> fragment-major smem (xor-ks swizzle) ----
    // A frag (mt16, ks): lane = g*4+c (g=row&7, c=(k&7)>>1), regs: hi + 2*hi16
    auto stA = [&](uint32_t* buf) {
#pragma unroll
        for (int i = 0; i < 4; i++) {
            int r  = (i << 5) + (tid >> 3);
            int k8 = tid & 7;
            int mt16 = r >> 4, r16 = r & 15, g = r16 & 7, hi = r16 >> 3;
            int ks = k8 >> 1, hi16 = k8 & 1;
            int reg = hi + (hi16 << 1);
            int fb = (mt16 * 4 + ks) * 128;
#pragma unroll
            for (int c = 0; c < 4; c++)
                buf[fb + (((g << 4) + (c << 2)) ^ (ks << 2)) + reg] = ua[i][c];
        }
    };
    // B frag (nt8, ks): lane = g*4+c (g=n&7, c=(k&7)>>1), regs: hi16
    auto stB = [&](uint32_t* buf) {
#pragma unroll
        for (int i = 0; i < 2; i++) {
            int n  = (i << 5) + (tid >> 3);
            int k8 = tid & 7;
            int nt8 = n >> 3, g = n & 7;
            int ks = k8 >> 1, reg = k8 & 1;
            int fb = (nt8 * 4 + ks) * 64;
#pragma unroll
            for (int c = 0; c < 4; c++)
                buf[fb + (((g << 3) + (c << 1)) ^ (ks << 1)) + reg] = ub[i][c];
        }
    };

    // prologue: tile 0
    ldA(0); ldB(0);
    stA(Asm[0]); stB(Bsm[0]);
    __syncthreads();

    for (int kc = 0; kc < nk; kc++) {
        const int cur = kc & 1;
        if (kc + 1 < nk) { ldA((kc + 1) << 6); ldB((kc + 1) << 6); }

        const uint32_t* Ac = Asm[cur];
        const uint32_t* Bc = Bsm[cur];
#pragma unroll
        for (int ks = 0; ks < 4; ks++) {
            uint32_t af[2][4];
#pragma unroll
            for (int mtl = 0; mtl < 2; mtl++) {
                int mt16 = wm * 2 + mtl;
                uint4 t = *(const uint4*)(Ac + (mt16 * 4 + ks) * 128 + ((lane << 2) ^ (ks << 2)));
                af[mtl][0] = t.x; af[mtl][1] = t.y; af[mtl][2] = t.z; af[mtl][3] = t.w;
            }
#pragma unroll
            for (int ntl = 0; ntl < 4; ntl++) {
                int nt8 = wn * 4 + ntl;
                uint2 bt = *(const uint2*)(Bc + (nt8 * 4 + ks) * 64 + ((lane << 1) ^ (ks << 1)));
                mma_f16_16x8x16(acc[0][ntl], af[0], bt.x, bt.y);
                mma_f16_16x8x16(acc[1][ntl], af[1], bt.x, bt.y);
            }
        }

        if (kc + 1 < nk) {
            stA(Asm[cur ^ 1]); stB(Bsm[cur ^ 1]);
            __syncthreads();
        }
    }

    // ---- epilogue: bias + activation, float2 stores ----
    const float* brow = bias ? bias + (size_t)blockIdx.z * sBias : nullptr;
    float* Cb = C + (size_t)blockIdx.z * sC;
#pragma unroll
    for (int mtl = 0; mtl < 2; mtl++) {
        size_t rA = row0 + wm * 32 + mtl * 16 + gq;
#pragma unroll
        for (int ntl = 0; ntl < 4; ntl++) {
            int col = n0 + wn * 32 + ntl * 8 + 2 * ctg;
            if (col >= Nreal) continue;
            float b0v = 0.f, b1v = 0.f;
            if (brow) { b0v = __ldg(brow + col); b1v = __ldg(brow + col + 1); }
            float v0 = acc[mtl][ntl][0] + b0v;
            float v1 = acc[mtl][ntl][1] + b1v;
            float v2 = acc[mtl][ntl][2] + b0v;
            float v3 = acc[mtl][ntl][3] + b1v;
            if (ACT == 1) {
                v0 = v0 > 0.f ? v0 : 0.f; v1 = v1 > 0.f ? v1 : 0.f;
                v2 = v2 > 0.f ? v2 : 0.f; v3 = v3 > 0.f ? v3 : 0.f;
            }
            if (ACT == 2) {
                v0 = v0 > 0.f ? v0 : expm1f(v0); v1 = v1 > 0.f ? v1 : expm1f(v1);
                v2 = v2 > 0.f ? v2 : expm1f(v2); v3 = v3 > 0.f ? v3 : expm1f(v3);
            }
            *(float2*)(Cb + rA * (size_t)ldc + col)       = make_float2(v0, v1);
            *(float2*)(Cb + (rA + 8) * (size_t)ldc + col) = make_float2(v2, v3);
        }
    }
}

// ---------------- pointwise / small kernels ---------------------------------
__device__ __forceinline__ float sigf(float x) { return 1.f / (1.f + expf(-x)); }

__global__ void zero_hc_kernel()
{
    int i = blockIdx.x * blockDim.x + threadIdx.x;
    if (i < BD * EE) { g_h0[i] = 0.f; g_c0[i] = 0.f; g_h1[i] = 0.f; g_c1[i] = 0.f; }
}

__global__ void lstm_cell0(const float* __restrict__ obs, const float* __restrict__ w_ih,
                           const float* __restrict__ b_ih, const float* __restrict__ b_hh, int t)
{
    int idx = blockIdx.x * blockDim.x + threadIdx.x;
    if (idx >= BD * EE) return;
    int b = idx >> 8, e = idx & 255;
    float x0 = obs[((long)b * TT + t) * 2 + 0];
    float x1 = obs[((long)b * TT + t) * 2 + 1];
    float gv[4];
#pragma unroll
    for (int q = 0; q < 4; q++) {
        int j = q * EE + e;
        gv[q] = g_gates[(long)b * GG + j] + x0 * w_ih[2 * j] + x1 * w_ih[2 * j + 1] + b_ih[j] + b_hh[j];
    }
    float ig = sigf(gv[0]), fg = sigf(gv[1]), gg = tanhf(gv[2]), og = sigf(gv[3]);
    float cn = fg * g_c0[idx] + ig * gg;
    float hn = og * tanhf(cn);
    g_c0[idx] = cn; g_h0[idx] = hn;
    g_ys0[(size_t)t * BD * EE + idx] = hn;
}

__global__ void lstm_cell1(const float* __restrict__ b_ih, const float* __restrict__ b_hh, int t)
{
    int idx = blockIdx.x * blockDim.x + threadIdx.x;
    if (idx >= BD * EE) return;
    int b = idx >> 8, e = idx & 255;
    const size_t xbase = ((size_t)t * BD + b) * GG;
    float gv[4];
#pragma unroll
    for (int q = 0; q < 4; q++) {
        int j = q * EE + e;
        gv[q] = g_gates[(long)b * GG + j] + g_xh1[xbase + j] + b_ih[j] + b_hh[j];
    }
    float ig = sigf(gv[0]), fg = sigf(gv[1]), gg = tanhf(gv[2]), og = sigf(gv[3]);
    float cn = fg * g_c1[idx] + ig * gg;
    float hn = og * tanhf(cn);
    g_c1[idx] = cn; g_h1[idx] = hn;
}

__global__ void ln_kernel(const float* __restrict__ x, const float* __restrict__ gam,
                          const float* __restrict__ bet, float* __restrict__ y)
{
    size_t warp = ((size_t)blockIdx.x * blockDim.x + threadIdx.x) >> 5;
    int lane = threadIdx.x & 31;
    if (warp >= (size_t)ROWS) return;
    const float* xr = x + warp * EE;
    float4 p0 = *(const float4*)(xr + lane * 8);
    float4 p1 = *(const float4*)(xr + lane * 8 + 4);
    float v[8] = {p0.x, p0.y, p0.z, p0.w, p1.x, p1.y, p1.z, p1.w};
    float s = 0.f, sq = 0.f;
#pragma unroll
    for (int i = 0; i < 8; i++) { s += v[i]; sq += v[i] * v[i]; }
#pragma unroll
    for (int o = 16; o; o >>= 1) {
        s  += __shfl_xor_sync(0xffffffffu, s,  o);
        sq += __shfl_xor_sync(0xffffffffu, sq, o);
    }
    float m   = s * (1.f / EE);
    float var = sq * (1.f / EE) - m * m;
    float inv = rsqrtf(var + 1e-5f);
    float* yr = y + warp * EE;
#pragma unroll
    for (int i = 0; i < 8; i++) {
        int e = lane * 8 + i;
        yr[e] = (v[i] - m) * inv * gam[e] + bet[e];
    }
}

__global__ void add_lastpos(float* __restrict__ pred, const float* __restrict__ obs)
{
    size_t idx = (size_t)blockIdx.x * blockDim.x + threadIdx.x;
    if (idx >= (size_t)PRED_ELEMS) return;
    size_t b = idx / (MM * FSX * 2);
    int c = (int)(idx & 1);
    pred[idx] += obs[(b * TT + (TT - 1)) * 2 + c];
}

__global__ void sc2_kernel(const float* __restrict__ s, const float* __restrict__ w,
                           const float* __restrict__ b2, float* __restrict__ outp)
{
    size_t gwarp = ((size_t)blockIdx.x * blockDim.x + threadIdx.x) >> 5;
    int lane = threadIdx.x & 31;
    if (gwarp >= (size_t)ROWS) return;
    const float* row = s + gwarp * 128;
    float4 a  = *(const float4*)(row + lane * 4);
    float4 ww = *(const float4*)(w   + lane * 4);
    float acc = a.x * ww.x + a.y * ww.y + a.z * ww.z + a.w * ww.w;
#pragma unroll
    for (int o = 16; o; o >>= 1) acc += __shfl_xor_sync(0xffffffffu, acc, o);
    if (lane == 0) outp[gwarp] = acc + b2[0];
}

// ---------------- host-side -------------------------------------------------
static void tcgemm(int act,
                   const float* A, long sA, int lda,
                   const float* W, long sW,
                   const float* bias, long sBias,
                   float* C, long sC, int ldc,
                   int Mrows, int N, int K, int nb)
{
    static bool attr_done = false;
    if (!attr_done) {
        cudaFuncSetAttribute(mma_gemm<0>, cudaFuncAttributeMaxDynamicSharedMemorySize, GEMM_SMEM);
        cudaFuncSetAttribute(mma_gemm<1>, cudaFuncAttributeMaxDynamicSharedMemorySize, GEMM_SMEM);
        cudaFuncSetAttribute(mma_gemm<2>, cudaFuncAttributeMaxDynamicSharedMemorySize, GEMM_SMEM);
        attr_done = true;
    }
    dim3 g((N + 63) / 64, Mrows / 128, nb), b(256);
    switch (act) {
    case 0: mma_gemm<0><<<g, b, GEMM_SMEM>>>(A, sA, lda, W, sW, bias, sBias, C, sC, ldc, N, K); break;
    case 1: mma_gemm<1><<<g, b, GEMM_SMEM>>>(A, sA, lda, W, sW, bias, sBias, C, sC, ldc, N, K); break;
    default: mma_gemm<2><<<g, b, GEMM_SMEM>>>(A, sA, lda, W, sW, bias, sBias, C, sC, ldc, N, K); break;
    }
}

extern "C" void kernel_launch(void* const* d_in, const int* in_sizes, int n_in,
                              void* d_out, int out_size)
{
    (void)in_sizes; (void)n_in; (void)out_size;
    const float* obs       = (const float*)d_in[0];
    const float* w_ih0     = (const float*)d_in[1];
    const float* w_hh0     = (const float*)d_in[2];
    const float* b_ih0     = (const float*)d_in[3];
    const float* b_hh0     = (const float*)d_in[4];
    const float* w_ih1     = (const float*)d_in[5];
    const float* w_hh1     = (const float*)d_in[6];
    const float* b_ih1     = (const float*)d_in[7];
    const float* b_hh1     = (const float*)d_in[8];
    const float* in_proj_w = (const float*)d_in[9];
    const float* in_proj_b = (const float*)d_in[10];
    const float* out_w     = (const float*)d_in[11];
    const float* out_b     = (const float*)d_in[12];
    const float* ln1_g     = (const float*)d_in[13];
    const float* ln1_b     = (const float*)d_in[14];
    const float* ffn_w1    = (const float*)d_in[15];
    const float* ffn_b1    = (const float*)d_in[16];
    const float* ffn_w2    = (const float*)d_in[17];
    const float* ffn_b2    = (const float*)d_in[18];
    const float* ln2_g     = (const float*)d_in[19];
    const float* ln2_b     = (const float*)d_in[20];
    const float* dec_w1    = (const float*)d_in[21];
    const float* dec_b1    = (const float*)d_in[22];
    const float* dec_w2    = (const float*)d_in[23];
    const float* dec_b2    = (const float*)d_in[24];
    const float* sc_w1     = (const float*)d_in[25];
    const float* sc_b1     = (const float*)d_in[26];
    const float* sc_w2     = (const float*)d_in[27];
    const float* sc_b2     = (const float*)d_in[28];
    float* out = (float*)d_out;

    float *ys0, *xh1, *h0, *h1, *gates, *bufA, *bufB, *bufC;
    cudaGetSymbolAddress((void**)&ys0,   g_ys0);
    cudaGetSymbolAddress((void**)&xh1,   g_xh1);
    cudaGetSymbolAddress((void**)&h0,    g_h0);
    cudaGetSymbolAddress((void**)&h1,    g_h1);
    cudaGetSymbolAddress((void**)&gates, g_gates);
    cudaGetSymbolAddress((void**)&bufA,  g_bufA);
    cudaGetSymbolAddress((void**)&bufB,  g_bufB);
    cudaGetSymbolAddress((void**)&bufC,  g_bufC);

    const int PT = 256;
    const int cellBlocks = (BD * EE + PT - 1) / PT;

    zero_hc_kernel<<<cellBlocks, PT>>>();

    // -------- LSTM layer 0 (x-proj fused into cell; K=2 trivial) --------
    for (int t = 0; t < TT; t++) {
        tcgemm(0, h0, 0, EE, w_hh0, 0, nullptr, 0, gates, 0, GG, BD, GG, EE, 1);
        lstm_cell0<<<cellBlocks, PT>>>(obs, w_ih0, b_ih0, b_hh0, t);
    }

    // -------- layer-1 input projections (all timesteps at once) --------
    tcgemm(0, ys0, 0, EE, w_ih1, 0, nullptr, 0, xh1, 0, GG, TT * BD, GG, EE, 1);

    // -------- LSTM layer 1 --------
    for (int t = 0; t < TT; t++) {
        tcgemm(0, h1, 0, EE, w_hh1, 0, nullptr, 0, gates, 0, GG, BD, GG, EE, 1);
        lstm_cell1<<<cellBlocks, PT>>>(b_ih1, b_hh1, t);
    }

    // -------- v projection (softmax over size-1 axis == 1 => ctx = v) --------
    tcgemm(0, h1, 0, EE,
           in_proj_w + (size_t)512 * EE, (long)768 * EE,
           in_proj_b + 512, 768,
           bufA, EE, MM * EE,
           BD, EE, EE, MM);

    // -------- per-mode output projection --------
    tcgemm(0, bufA, EE, MM * EE,
           out_w, (long)EE * EE,
           out_b, EE,
           bufB, EE, MM * EE,
           BD, EE, EE, MM);

    // -------- LN1 --------
    {
        dim3 g((ROWS * 32 + 255) / 256), b(256);
        ln_kernel<<<g, b>>>(bufB, ln1_g, ln1_b, bufA);
    }

    // -------- FFN --------
    tcgemm(1, bufA, 0, EE,   ffn_w1, 0, ffn_b1, 0, bufC, 0, 1024, ROWS, 1024, EE,   1);
    tcgemm(0, bufC, 0, 1024, ffn_w2, 0, ffn_b2, 0, bufB, 0, EE,   ROWS, EE,   1024, 1);

    // -------- LN2 -> mm_emb --------
    {
        dim3 g((ROWS * 32 + 255) / 256), b(256);
        ln_kernel<<<g, b>>>(bufB, ln2_g, ln2_b, bufA);
    }

    // -------- decoder head --------
    tcgemm(2, bufA, 0, EE, dec_w1, 0, dec_b1, 0, bufC, 0, 512, ROWS, 512, EE, 1);
    tcgemm(0, bufC, 0, 512, dec_w2, 0, dec_b2, 0, out, 0, 24, ROWS, 24, 512, 1);
    {
        dim3 g((PRED_ELEMS + 255) / 256), b(256);
        add_lastpos<<<g, b>>>(out, obs);
    }

    // -------- score head --------
    tcgemm(2, bufA, 0, EE, sc_w1, 0, sc_b1, 0, bufB, 0, 128, ROWS, 128, EE, 1);
    {
        dim3 g((ROWS * 32 + 255) / 256), b(256);
        sc2_kernel<<<g, b>>>(bufB, sc_w2, sc_b2, out + PRED_ELEMS);
    }
}

// round 9
// speedup vs baseline: 5.5851x; 1.8140x over previous
#include <cuda_runtime.h>
#include <cuda_fp16.h>
#include <cstdint>
#include <math.h>

// Problem dims
#define BD   8192
#define TT   8
#define EE   256
#define GG   1024          // 4*E
#define MM   20
#define ROWS (BD*MM)       // 163840
#define FSX  12
#define PRED_ELEMS (BD*MM*FSX*2)   // 3932160

// ---------------- fp16 weight arena offsets (in halves) ----------------------
#define WH_HH0  0
#define WH_IH1  262144
#define WH_HH1  524288
#define WH_VPJ  786432        // 20 x 256 x 256
#define WH_OUTW 2097152       // 20 x 256 x 256
#define WH_F1   3407872
#define WH_F2   3670016
#define WH_D1   3932160
#define WH_D2   4063232       // 24 x 512
#define WH_SC1  4075520
#define WH_TOT  4108288

// ---------------- scratch (static device globals; no allocation) -------------
__device__ __half g_wh[WH_TOT];
__device__ __half g_h0h[BD*EE];
__device__ __half g_h1h[BD*EE];
__device__ __half g_ys0h[(size_t)TT*BD*EE];
__device__ __half g_ctxh[(size_t)ROWS*EE];
__device__ __half g_lnh[(size_t)ROWS*EE];
__device__ __half g_ffnh[(size_t)ROWS*1024];
__device__ __half g_sch[(size_t)ROWS*128];
__device__ float  g_gates[(size_t)BD*GG];
__device__ float  g_xh1[(size_t)TT*BD*GG];
__device__ float  g_c0[BD*EE];
__device__ float  g_c1[BD*EE];
__device__ float  g_bufB[(size_t)ROWS*EE];

// ======================= helpers ============================================
__device__ __forceinline__ uint32_t smem_u32(const void* p) {
    uint32_t a;
    asm("{ .reg .u64 t; cvta.to.shared.u64 t, %1; cvt.u32.u64 %0, t; }" : "=r"(a) : "l"(p));
    return a;
}
__device__ __forceinline__ void cp16(uint32_t dst, const void* src, bool pred) {
    int sz = pred ? 16 : 0;
    asm volatile("cp.async.ca.shared.global [%0], [%1], 16, %2;" :: "r"(dst), "l"(src), "r"(sz));
}
__device__ __forceinline__ void mma_f16(float* d, const uint32_t* a, uint32_t b0, uint32_t b1) {
    asm volatile(
        "mma.sync.aligned.m16n8k16.row.col.f32.f16.f16.f32 "
        "{%0,%1,%2,%3}, {%4,%5,%6,%7}, {%8,%9}, {%0,%1,%2,%3};"
        : "+f"(d[0]), "+f"(d[1]), "+f"(d[2]), "+f"(d[3])
        : "r"(a[0]), "r"(a[1]), "r"(a[2]), "r"(a[3]), "r"(b0), "r"(b1));
}

// ======================= fp16 GEMM: cp.async + ldmatrix =====================
// C[r,n] = act( sum_k A[r,k]*W[n,k] + bias[n] )
// A,W fp16 in global (K-contiguous). CTA tile 128x128x64, 8 warps (4M x 2N),
// warp tile 32x64, 3-stage cp.async pipeline, XOR-swizzled smem rows,
// ldmatrix.x4 fragment loads, fp32 accumulate.
// ACT: 0 none, 1 relu, 2 elu, 3 none+lastpos(dec2).  OUTH: 1 = fp16 C.
#define STAGES 3
#define STAGE_BYTES 32768
#define GEMM_SMEM (STAGES*STAGE_BYTES)   // 98304

template<int ACT, int OUTH>
__global__ void __launch_bounds__(256, 2)
hgemm(const __half* __restrict__ A, long sA, int lda,
      const __half* __restrict__ W, long sW,
      const float* __restrict__ bias, long sBias,
      void* __restrict__ Cv, long sC, int ldc,
      int Nreal, int K, const float* __restrict__ obs)
{
    extern __shared__ char smem[];
    const uint32_t smBase = smem_u32(smem);

    const int tid = threadIdx.x, lane = tid & 31, wid = tid >> 5;
    const int wm = wid >> 1, wn = wid & 1;          // 4 M-warps x 2 N-warps
    const int gq = lane >> 2, ctg = lane & 3;

    const __half* Ab = A + (size_t)blockIdx.z * sA;
    const __half* Wb = W + (size_t)blockIdx.z * sW;
    const size_t row0 = (size_t)blockIdx.y * 128;
    const int    n0   = blockIdx.x * 128;
    const int    nk   = K >> 6;

    const int ldRow = tid >> 3;       // 0..31
    const int ldU   = tid & 7;        // 16B unit within 128B row

    auto issue = [&](int kc, int stage) {
        uint32_t aS = smBase + stage * STAGE_BYTES;
        uint32_t bS = aS + 16384;
        int kt = kc << 6;
#pragma unroll
        for (int i = 0; i < 4; i++) {
            int r = (i << 5) + ldRow;
            uint32_t d = aS + r * 128 + ((ldU ^ (r & 7)) << 4);
            cp16(d, Ab + (row0 + r) * (size_t)lda + kt + (ldU << 3), true);
        }
#pragma unroll
        for (int i = 0; i < 4; i++) {
            int r = (i << 5) + ldRow;
            uint32_t d = bS + r * 128 + ((ldU ^ (r & 7)) << 4);
            cp16(d, Wb + (size_t)(n0 + r) * K + kt + (ldU << 3), (n0 + r) < Nreal);
        }
    };

    float acc[2][8][4];
#pragma unroll
    for (int i = 0; i < 2; i++)
#pragma unroll
        for (int j = 0; j < 8; j++)
#pragma unroll
            for (int q = 0; q < 4; q++) acc[i][j][q] = 0.f;

    // prologue: stages 0,1
    issue(0, 0);
    asm volatile("cp.async.commit_group;" ::: "memory");
    if (nk > 1) issue(1, 1);
    asm volatile("cp.async.commit_group;" ::: "memory");

    // per-lane ldmatrix geometry
    const int sub = lane >> 3, rin = lane & 7;
    const int arow0 = wm * 32 + ((sub & 1) << 3) + rin;   // + mtl*16
    const int auSel = sub >> 1;
    const int brow0 = wn * 64 + ((sub >> 1) << 3) + rin;  // + pair*16
    const int buSel = sub & 1;

    for (int kc = 0; kc < nk; kc++) {
        asm volatile("cp.async.wait_group 1;" ::: "memory");
        __syncthreads();
        if (kc + 2 < nk) issue(kc + 2, (kc + 2) % STAGES);
        asm volatile("cp.async.commit_group;" ::: "memory");

        uint32_t aS = smBase + (kc % STAGES) * STAGE_BYTES;
        uint32_t bS = aS + 16384;
#pragma unroll
        for (int ks = 0; ks < 4; ks++) {
            uint32_t af[2][4];
#pragma unroll
            for (int mtl = 0; mtl < 2; mtl++) {
                int row = arow0 + mtl * 16;
                int unit = (2 * ks + auSel) ^ (row & 7);
                uint32_t addr = aS + row * 128 + (unit << 4);
                asm volatile("ldmatrix.sync.aligned.m8n8.x4.shared.b16 {%0,%1,%2,%3}, [%4];"
                    : "=r"(af[mtl][0]), "=r"(af[mtl][1]), "=r"(af[mtl][2]), "=r"(af[mtl][3])
                    : "r"(addr));
            }
#pragma unroll
            for (int p = 0; p < 4; p++) {
                int row = brow0 + p * 16;
                int unit = (2 * ks + buSel) ^ (row & 7);
                uint32_t addr = bS + row * 128 + (unit << 4);
                uint32_t bf[4];
                asm volatile("ldmatrix.sync.aligned.m8n8.x4.shared.b16 {%0,%1,%2,%3}, [%4];"
                    : "=r"(bf[0]), "=r"(bf[1]), "=r"(bf[2]), "=r"(bf[3])
                    : "r"(addr));
                mma_f16(acc[0][2 * p],     af[0], bf[0], bf[1]);
                mma_f16(acc[0][2 * p + 1], af[0], bf[2], bf[3]);
                mma_f16(acc[1][2 * p],     af[1], bf[0], bf[1]);
                mma_f16(acc[1][2 * p + 1], af[1], bf[2], bf[3]);
            }
        }
    }

    // ---- epilogue ----
    const float* brow = bias ? bias + (size_t)blockIdx.z * sBias : nullptr;
#pragma unroll
    for (int mtl = 0; mtl < 2; mtl++) {
#pragma unroll
        for (int half_ = 0; half_ < 2; half_++) {
            size_t r = row0 + wm * 32 + mtl * 16 + gq + half_ * 8;
#pragma unroll
            for (int ntl = 0; ntl < 8; ntl++) {
                int col = n0 + wn * 64 + ntl * 8 + 2 * ctg;
                if (col >= Nreal) continue;
                float v0 = acc[mtl][ntl][half_ * 2 + 0];
                float v1 = acc[mtl][ntl][half_ * 2 + 1];
                if (brow) { v0 += __ldg(brow + col); v1 += __ldg(brow + col + 1); }
                if (ACT == 1) { v0 = v0 > 0.f ? v0 : 0.f; v1 = v1 > 0.f ? v1 : 0.f; }
                if (ACT == 2) { v0 = v0 > 0.f ? v0 : expm1f(v0); v1 = v1 > 0.f ? v1 : expm1f(v1); }
                if (ACT == 3) {
                    const float* ob = obs + (r / MM) * (TT * 2) + (TT - 1) * 2;
                    v0 += __ldg(ob + (col & 1));
                    v1 += __ldg(ob + ((col + 1) & 1));
                }
                if (OUTH) {
                    __half2 h = __floats2half2_rn(v0, v1);
                    *(__half2*)((__half*)Cv + (size_t)blockIdx.z * sC + r * (size_t)ldc + col) = h;
                } else {
                    *(float2*)((float*)Cv + (size_t)blockIdx.z * sC + r * (size_t)ldc + col) = make_float2(v0, v1);
                }
            }
        }
    }
}

// ---------------- conversion & pointwise kernels -----------------------------
__global__ void cvt_f2h(const float* __restrict__ src, __half* __restrict__ dst,
                        long srcStride, long dstStride, int chunk, long total)
{
    for (long i = (long)blockIdx.x * blockDim.x + threadIdx.x; i < total;
         i += (long)gridDim.x * blockDim.x) {
        long c = i / chunk; int j = (int)(i - c * chunk);
        dst[c * dstStride + j] = __float2half(src[c * srcStride + j]);
    }
}

__device__ __forceinline__ float sigf(float x) { return 1.f / (1.f + expf(-x)); }

__global__ void zero_hc_kernel()
{
    int i = blockIdx.x * blockDim.x + threadIdx.x;
    if (i < BD * EE) {
        g_c0[i] = 0.f; g_c1[i] = 0.f;
        g_h0h[i] = __float2half(0.f); g_h1h[i] = __float2half(0.f);
    }
}

__global__ void lstm_cell0(const float* __restrict__ obs, const float* __restrict__ w_ih,
                           const float* __restrict__ b_ih, const float* __restrict__ b_hh, int t)
{
    int idx = blockIdx.x * blockDim.x + threadIdx.x;
    if (idx >= BD * EE) return;
    int b = idx >> 8, e = idx & 255;
    float x0 = obs[((long)b * TT + t) * 2 + 0];
    float x1 = obs[((long)b * TT + t) * 2 + 1];
    float gv[4];
#pragma unroll
    for (int q = 0; q < 4; q++) {
        int j = q * EE + e;
        gv[q] = g_gates[(long)b * GG + j] + x0 * w_ih[2 * j] + x1 * w_ih[2 * j + 1] + b_ih[j] + b_hh[j];
    }
    float ig = sigf(gv[0]), fg = sigf(gv[1]), gg = tanhf(gv[2]), og = sigf(gv[3]);
    float cn = fg * g_c0[idx] + ig * gg;
    float hn = og * tanhf(cn);
    g_c0[idx] = cn;
    __half hh = __float2half(hn);
    g_h0h[idx] = hh;
    g_ys0h[(size_t)t * BD * EE + idx] = hh;
}

__global__ void lstm_cell1(const float* __restrict__ b_ih, const float* __restrict__ b_hh, int t)
{
    int idx = blockIdx.x * blockDim.x + threadIdx.x;
    if (idx >= BD * EE) return;
    int b = idx >> 8, e = idx & 255;
    const size_t xbase = ((size_t)t * BD + b) * GG;
    float gv[4];
#pragma unroll
    for (int q = 0; q < 4; q++) {
        int j = q * EE + e;
        gv[q] = g_gates[(long)b * GG + j] + g_xh1[xbase + j] + b_ih[j] + b_hh[j];
    }
    float ig = sigf(gv[0]), fg = sigf(gv[1]), gg = tanhf(gv[2]), og = sigf(gv[3]);
    float cn = fg * g_c1[idx] + ig * gg;
    float hn = og * tanhf(cn);
    g_c1[idx] = cn;
    g_h1h[idx] = __float2half(hn);
}

// LayerNorm over E=256 -> fp16 output
__global__ void ln_kernel_h(const float* __restrict__ x, const float* __restrict__ gam,
                            const float* __restrict__ bet, __half* __restrict__ y)
{
    size_t warp = ((size_t)blockIdx.x * blockDim.x + threadIdx.x) >> 5;
    int lane = threadIdx.x & 31;
    if (warp >= (size_t)ROWS) return;
    const float* xr = x + warp * EE;
    float4 p0 = *(const float4*)(xr + lane * 8);
    float4 p1 = *(const float4*)(xr + lane * 8 + 4);
    float v[8] = {p0.x, p0.y, p0.z, p0.w, p1.x, p1.y, p1.z, p1.w};
    float s = 0.f, sq = 0.f;
#pragma unroll
    for (int i = 0; i < 8; i++) { s += v[i]; sq += v[i] * v[i]; }
#pragma unroll
    for (int o = 16; o; o >>= 1) {
        s  += __shfl_xor_sync(0xffffffffu, s,  o);
        sq += __shfl_xor_sync(0xffffffffu, sq, o);
    }
    float m   = s * (1.f / EE);
    float var = sq * (1.f / EE) - m * m;
    float inv = rsqrtf(var + 1e-5f);
    __half2 o4[4];
#pragma unroll
    for (int i = 0; i < 4; i++) {
        int e = lane * 8 + 2 * i;
        float a0 = (v[2 * i]     - m) * inv * gam[e]     + bet[e];
        float a1 = (v[2 * i + 1] - m) * inv * gam[e + 1] + bet[e + 1];
        o4[i] = __floats2half2_rn(a0, a1);
    }
    *(uint4*)(y + warp * EE + lane * 8) = *(uint4*)o4;
}

// score head final dot (fp16 input)
__global__ void sc2_kernel(const __half* __restrict__ s, const float* __restrict__ w,
                           const float* __restrict__ b2, float* __restrict__ outp)
{
    size_t gwarp = ((size_t)blockIdx.x * blockDim.x + threadIdx.x) >> 5;
    int lane = threadIdx.x & 31;
    if (gwarp >= (size_t)ROWS) return;
    const __half2* row = (const __half2*)(s + gwarp * 128);
    __half2 h0 = row[lane * 2], h1 = row[lane * 2 + 1];
    float2 f0 = __half22float2(h0), f1 = __half22float2(h1);
    float4 ww = *(const float4*)(w + lane * 4);
    float acc = f0.x * ww.x + f0.y * ww.y + f1.x * ww.z + f1.y * ww.w;
#pragma unroll
    for (int o = 16; o; o >>= 1) acc += __shfl_xor_sync(0xffffffffu, acc, o);
    if (lane == 0) outp[gwarp] = acc + b2[0];
}

// ---------------- host-side -------------------------------------------------
static void hgemm_go(int mode,
                     const __half* A, long sA, int lda,
                     const __half* W, long sW,
                     const float* bias, long sBias,
                     void* C, long sC, int ldc,
                     int Mrows, int N, int K, int nb, const float* obs)
{
    static bool attr_done = false;
    if (!attr_done) {
        cudaFuncSetAttribute(hgemm<0,0>, cudaFuncAttributeMaxDynamicSharedMemorySize, GEMM_SMEM);
        cudaFuncSetAttribute(hgemm<0,1>, cudaFuncAttributeMaxDynamicSharedMemorySize, GEMM_SMEM);
        cudaFuncSetAttribute(hgemm<1,1>, cudaFuncAttributeMaxDynamicSharedMemorySize, GEMM_SMEM);
        cudaFuncSetAttribute(hgemm<2,1>, cudaFuncAttributeMaxDynamicSharedMemorySize, GEMM_SMEM);
        cudaFuncSetAttribute(hgemm<3,0>, cudaFuncAttributeMaxDynamicSharedMemorySize, GEMM_SMEM);
        attr_done = true;
    }
    dim3 g((N + 127) / 128, Mrows / 128, nb), b(256);
    switch (mode) {
    case 0: hgemm<0,0><<<g,b,GEMM_SMEM>>>(A,sA,lda,W,sW,bias,sBias,C,sC,ldc,N,K,obs); break;
    case 1: hgemm<0,1><<<g,b,GEMM_SMEM>>>(A,sA,lda,W,sW,bias,sBias,C,sC,ldc,N,K,obs); break;
    case 2: hgemm<1,1><<<g,b,GEMM_SMEM>>>(A,sA,lda,W,sW,bias,sBias,C,sC,ldc,N,K,obs); break;
    case 3: hgemm<2,1><<<g,b,GEMM_SMEM>>>(A,sA,lda,W,sW,bias,sBias,C,sC,ldc,N,K,obs); break;
    default: hgemm<3,0><<<g,b,GEMM_SMEM>>>(A,sA,lda,W,sW,bias,sBias,C,sC,ldc,N,K,obs); break;
    }
}

static void cvt(const float* src, __half* dst, long ss, long ds, int chunk, long total)
{
    int grid = (int)((total + 255) / 256);
    if (grid > 4096) grid = 4096;
    cvt_f2h<<<grid, 256>>>(src, dst, ss, ds, chunk, total);
}

extern "C" void kernel_launch(void* const* d_in, const int* in_sizes, int n_in,
                              void* d_out, int out_size)
{
    (void)in_sizes; (void)n_in; (void)out_size;
    const float* obs       = (const float*)d_in[0];
    const float* w_ih0     = (const float*)d_in[1];
    const float* w_hh0     = (const float*)d_in[2];
    const float* b_ih0     = (const float*)d_in[3];
    const float* b_hh0     = (const float*)d_in[4];
    const float* w_ih1     = (const float*)d_in[5];
    const float* w_hh1     = (const float*)d_in[6];
    const float* b_ih1     = (const float*)d_in[7];
    const float* b_hh1     = (const float*)d_in[8];
    const float* in_proj_w = (const float*)d_in[9];
    const float* in_proj_b = (const float*)d_in[10];
    const float* out_w     = (const float*)d_in[11];
    const float* out_b     = (const float*)d_in[12];
    const float* ln1_g     = (const float*)d_in[13];
    const float* ln1_b     = (const float*)d_in[14];
    const float* ffn_w1    = (const float*)d_in[15];
    const float* ffn_b1    = (const float*)d_in[16];
    const float* ffn_w2    = (const float*)d_in[17];
    const float* ffn_b2    = (const float*)d_in[18];
    const float* ln2_g     = (const float*)d_in[19];
    const float* ln2_b     = (const float*)d_in[20];
    const float* dec_w1    = (const float*)d_in[21];
    const float* dec_b1    = (const float*)d_in[22];
    const float* dec_w2    = (const float*)d_in[23];
    const float* dec_b2    = (const float*)d_in[24];
    const float* sc_w1     = (const float*)d_in[25];
    const float* sc_b1     = (const float*)d_in[26];
    const float* sc_w2     = (const float*)d_in[27];
    const float* sc_b2     = (const float*)d_in[28];
    float* out = (float*)d_out;

    __half *wh, *h0h, *h1h, *ys0h, *ctxh, *lnh, *ffnh, *sch;
    float *gates, *xh1, *bufB;
    cudaGetSymbolAddress((void**)&wh,    g_wh);
    cudaGetSymbolAddress((void**)&h0h,   g_h0h);
    cudaGetSymbolAddress((void**)&h1h,   g_h1h);
    cudaGetSymbolAddress((void**)&ys0h,  g_ys0h);
    cudaGetSymbolAddress((void**)&ctxh,  g_ctxh);
    cudaGetSymbolAddress((void**)&lnh,   g_lnh);
    cudaGetSymbolAddress((void**)&ffnh,  g_ffnh);
    cudaGetSymbolAddress((void**)&sch,   g_sch);
    cudaGetSymbolAddress((void**)&gates, g_gates);
    cudaGetSymbolAddress((void**)&xh1,   g_xh1);
    cudaGetSymbolAddress((void**)&bufB,  g_bufB);

    // -------- weight conversions (fp32 -> fp16 arena) --------
    cvt(w_hh0,  wh + WH_HH0,  0, 0, 262144, 262144);
    cvt(w_ih1,  wh + WH_IH1,  0, 0, 262144, 262144);
    cvt(w_hh1,  wh + WH_HH1,  0, 0, 262144, 262144);
    cvt(in_proj_w + (size_t)512 * EE, wh + WH_VPJ, (long)768 * EE, 65536, 65536, (long)MM * 65536);
    cvt(out_w,  wh + WH_OUTW, 0, 0, 1310720, 1310720);
    cvt(ffn_w1, wh + WH_F1,   0, 0, 262144, 262144);
    cvt(ffn_w2, wh + WH_F2,   0, 0, 262144, 262144);
    cvt(dec_w1, wh + WH_D1,   0, 0, 131072, 131072);
    cvt(dec_w2, wh + WH_D2,   0, 0, 12288, 12288);
    cvt(sc_w1,  wh + WH_SC1,  0, 0, 32768, 32768);

    const int PT = 256;
    const int cellBlocks = (BD * EE + PT - 1) / PT;
    zero_hc_kernel<<<cellBlocks, PT>>>();

    // -------- LSTM layer 0 (x-proj fused into cell; K=2 trivial) --------
    for (int t = 0; t < TT; t++) {
        hgemm_go(0, h0h, 0, EE, wh + WH_HH0, 0, nullptr, 0, gates, 0, GG, BD, GG, EE, 1, nullptr);
        lstm_cell0<<<cellBlocks, PT>>>(obs, w_ih0, b_ih0, b_hh0, t);
    }

    // -------- layer-1 input projections (all timesteps at once) --------
    hgemm_go(0, ys0h, 0, EE, wh + WH_IH1, 0, nullptr, 0, xh1, 0, GG, TT * BD, GG, EE, 1, nullptr);

    // -------- LSTM layer 1 --------
    for (int t = 0; t < TT; t++) {
        hgemm_go(0, h1h, 0, EE, wh + WH_HH1, 0, nullptr, 0, gates, 0, GG, BD, GG, EE, 1, nullptr);
        lstm_cell1<<<cellBlocks, PT>>>(b_ih1, b_hh1, t);
    }

    // -------- v projection (softmax over size-1 axis == 1 => ctx = v) --------
    hgemm_go(1, h1h, 0, EE,
             wh + WH_VPJ, 65536,
             in_proj_b + 512, 768,
             ctxh, EE, MM * EE,
             BD, EE, EE, MM, nullptr);

    // -------- per-mode output projection --------
    hgemm_go(0, ctxh, EE, MM * EE,
             wh + WH_OUTW, 65536,
             out_b, EE,
             bufB, EE, MM * EE,
             BD, EE, EE, MM, nullptr);

    // -------- LN1 -> fp16 --------
    {
        dim3 g((ROWS * 32 + 255) / 256), b(256);
        ln_kernel_h<<<g, b>>>(bufB, ln1_g, ln1_b, lnh);
    }

    // -------- FFN --------
    hgemm_go(2, lnh, 0, EE,   wh + WH_F1, 0, ffn_b1, 0, ffnh, 0, 1024, ROWS, 1024, EE,   1, nullptr);
    hgemm_go(0, ffnh, 0, 1024, wh + WH_F2, 0, ffn_b2, 0, bufB, 0, EE,  ROWS, EE,   1024, 1, nullptr);

    // -------- LN2 -> mm_emb (fp16) --------
    {
        dim3 g((ROWS * 32 + 255) / 256), b(256);
        ln_kernel_h<<<g, b>>>(bufB, ln2_g, ln2_b, lnh);
    }

    // -------- decoder head (lastpos fused into dec2 epilogue) --------
    hgemm_go(3, lnh, 0, EE, wh + WH_D1, 0, dec_b1, 0, ffnh, 0, 512, ROWS, 512, EE, 1, nullptr);
    hgemm_go(4, ffnh, 0, 512, wh + WH_D2, 0, dec_b2, 0, out, 0, 24, ROWS, 24, 512, 1, obs);

    // -------- score head --------
    hgemm_go(3, lnh, 0, EE, wh + WH_SC1, 0, sc_b1, 0, sch, 0, 128, ROWS, 128, EE, 1, nullptr);
    {
        dim3 g((ROWS * 32 + 255) / 256), b(256);
        sc2_kernel<<<g, b>>>(sch, sc_w2, sc_b2, out + PRED_ELEMS);
    }
}